// round 3
// baseline (speedup 1.0000x reference)
#include <cuda_runtime.h>
#include <cuda_bf16.h>

#define N_NODES   100000
#define N_EDGES   3200000
#define D_IN      128
#define D_H0      64
#define D_H1      32
#define N_GRAPHS  1024
#define N_CLASSES 16

// ---------------- scratch (static __device__, allocation-free) ----------------
__device__ float g_deg[N_NODES];          // degree (incl. self loop)
__device__ float g_inv[N_NODES];          // rsqrt(deg)
__device__ float g_hw0[N_NODES * D_H0];   // x @ W0
__device__ float g_agg0[N_NODES * D_H0];  // aggregated -> relu -> h0 (in place)
__device__ float g_hw1[N_NODES * D_H1];   // h0 @ W1
__device__ float g_agg1[N_NODES * D_H1];  // aggregated -> relu -> h1 (in place)

// ---------------- degree ----------------
__global__ void k_deg_init() {
    int i = blockIdx.x * blockDim.x + threadIdx.x;
    if (i < N_NODES) g_deg[i] = 1.0f;  // self loop
}

__global__ void k_deg_count(const int* __restrict__ ei) {
    int e = blockIdx.x * blockDim.x + threadIdx.x;
    if (e < N_EDGES) atomicAdd(&g_deg[ei[e]], 1.0f);  // ei[0][e] = target row
}

__global__ void k_inv() {
    int i = blockIdx.x * blockDim.x + threadIdx.x;
    if (i < N_NODES) g_inv[i] = rsqrtf(g_deg[i]);
}

// ---------------- GEMM0: hw0 = x[N,128] @ W0[128,64] ----------------
// 256 threads = 4 row-groups x 64 cols; 64 rows per block; W0 in smem.
__global__ void k_gemm0(const float* __restrict__ x, const float* __restrict__ W0) {
    __shared__ float Ws[D_IN * D_H0];  // 32 KB
    for (int idx = threadIdx.x; idx < D_IN * D_H0; idx += 256) Ws[idx] = W0[idx];
    __syncthreads();

    const int c  = threadIdx.x & 63;
    const int rg = threadIdx.x >> 6;       // 0..3
    const int rbase = blockIdx.x * 64;

    for (int rr = rg; rr < 64; rr += 4) {
        int row = rbase + rr;
        if (row >= N_NODES) break;
        const float4* xr = (const float4*)(x + (size_t)row * D_IN);
        float s = 0.f;
#pragma unroll
        for (int k4 = 0; k4 < D_IN / 4; k4++) {
            float4 v = xr[k4];  // uniform within warp -> L1 broadcast
            s += v.x * Ws[(k4 * 4 + 0) * 64 + c];
            s += v.y * Ws[(k4 * 4 + 1) * 64 + c];
            s += v.z * Ws[(k4 * 4 + 2) * 64 + c];
            s += v.w * Ws[(k4 * 4 + 3) * 64 + c];
        }
        g_hw0[(size_t)row * 64 + c] = s;
    }
}

// ---------------- self-loop init: agg[i] = hw[i] * (1/deg[i]) ----------------
__global__ void k_self0() {
    unsigned gid = blockIdx.x * blockDim.x + threadIdx.x;  // N*16 float4 lanes
    if (gid >= N_NODES * 16u) return;
    int i = gid >> 4, j = gid & 15;
    float inv = g_inv[i];
    float s = inv * inv;
    float4 v = ((const float4*)g_hw0)[(size_t)i * 16 + j];
    float4 o = {v.x * s, v.y * s, v.z * s, v.w * s};
    ((float4*)g_agg0)[(size_t)i * 16 + j] = o;
}

__global__ void k_self1() {
    unsigned gid = blockIdx.x * blockDim.x + threadIdx.x;  // N*8 float4 lanes
    if (gid >= N_NODES * 8u) return;
    int i = gid >> 3, j = gid & 7;
    float inv = g_inv[i];
    float s = inv * inv;
    float4 v = ((const float4*)g_hw1)[(size_t)i * 8 + j];
    float4 o = {v.x * s, v.y * s, v.z * s, v.w * s};
    ((float4*)g_agg1)[(size_t)i * 8 + j] = o;
}

// ---------------- vector red helper ----------------
__device__ __forceinline__ void red_add_v4(float* dst, float4 m) {
    asm volatile("red.global.add.v4.f32 [%0], {%1,%2,%3,%4};"
                 :: "l"(dst), "f"(m.x), "f"(m.y), "f"(m.z), "f"(m.w) : "memory");
}

// ---------------- edge scatter, layer 0: 16 float4-lanes per edge ----------------
__global__ void k_scat0(const int* __restrict__ ei) {
    unsigned gid = blockIdx.x * blockDim.x + threadIdx.x;
    if (gid >= (unsigned)N_EDGES * 16u) return;
    int e = gid >> 4, j = gid & 15;
    int r = ei[e];
    int c = ei[N_EDGES + e];
    float nrm = g_inv[r] * g_inv[c];
    float4 v = ((const float4*)g_hw0)[(size_t)c * 16 + j];
    float4 m = {v.x * nrm, v.y * nrm, v.z * nrm, v.w * nrm};
    red_add_v4(g_agg0 + (size_t)r * 64 + j * 4, m);
}

// ---------------- edge scatter, layer 1: 8 float4-lanes per edge ----------------
__global__ void k_scat1(const int* __restrict__ ei) {
    unsigned gid = blockIdx.x * blockDim.x + threadIdx.x;
    if (gid >= (unsigned)N_EDGES * 8u) return;
    int e = gid >> 3, j = gid & 7;
    int r = ei[e];
    int c = ei[N_EDGES + e];
    float nrm = g_inv[r] * g_inv[c];
    float4 v = ((const float4*)g_hw1)[(size_t)c * 8 + j];
    float4 m = {v.x * nrm, v.y * nrm, v.z * nrm, v.w * nrm};
    red_add_v4(g_agg1 + (size_t)r * 32 + j * 4, m);
}

// ---------------- bias + relu (in place) ----------------
__global__ void k_relu0(const float* __restrict__ b0) {
    unsigned gid = blockIdx.x * blockDim.x + threadIdx.x;  // N*16 float4 lanes
    if (gid >= N_NODES * 16u) return;
    int j = gid & 15;
    float4 b = ((const float4*)b0)[j];
    float4 v = ((float4*)g_agg0)[gid];
    v.x = fmaxf(v.x + b.x, 0.f); v.y = fmaxf(v.y + b.y, 0.f);
    v.z = fmaxf(v.z + b.z, 0.f); v.w = fmaxf(v.w + b.w, 0.f);
    ((float4*)g_agg0)[gid] = v;
}

__global__ void k_relu1(const float* __restrict__ b1) {
    unsigned gid = blockIdx.x * blockDim.x + threadIdx.x;  // N*8 float4 lanes
    if (gid >= N_NODES * 8u) return;
    int j = gid & 7;
    float4 b = ((const float4*)b1)[j];
    float4 v = ((float4*)g_agg1)[gid];
    v.x = fmaxf(v.x + b.x, 0.f); v.y = fmaxf(v.y + b.y, 0.f);
    v.z = fmaxf(v.z + b.z, 0.f); v.w = fmaxf(v.w + b.w, 0.f);
    ((float4*)g_agg1)[gid] = v;
}

// ---------------- GEMM1: hw1 = h0[N,64] @ W1[64,32] ----------------
// 256 threads = 8 row-groups x 32 cols; 128 rows per block; W1 in smem.
__global__ void k_gemm1(const float* __restrict__ W1) {
    __shared__ float Ws[D_H0 * D_H1];  // 8 KB
    for (int idx = threadIdx.x; idx < D_H0 * D_H1; idx += 256) Ws[idx] = W1[idx];
    __syncthreads();

    const int c  = threadIdx.x & 31;
    const int rg = threadIdx.x >> 5;       // 0..7
    const int rbase = blockIdx.x * 128;

    for (int rr = rg; rr < 128; rr += 8) {
        int row = rbase + rr;
        if (row >= N_NODES) break;
        const float4* xr = (const float4*)(g_agg0 + (size_t)row * D_H0);
        float s = 0.f;
#pragma unroll
        for (int k4 = 0; k4 < D_H0 / 4; k4++) {
            float4 v = xr[k4];
            s += v.x * Ws[(k4 * 4 + 0) * 32 + c];
            s += v.y * Ws[(k4 * 4 + 1) * 32 + c];
            s += v.z * Ws[(k4 * 4 + 2) * 32 + c];
            s += v.w * Ws[(k4 * 4 + 3) * 32 + c];
        }
        g_hw1[(size_t)row * 32 + c] = s;
    }
}

// ---------------- mean pool per graph + dense head ----------------
// node_graph_index is sorted -> binary search segment bounds, no atomics.
__global__ void k_pool(const int* __restrict__ ngi,
                       const float* __restrict__ Wd,
                       const float* __restrict__ bd,
                       float* __restrict__ out) {
    const int g = blockIdx.x;

    // lower_bound(g) and lower_bound(g+1) over sorted int32 array
    int lo = 0, hi = N_NODES;
    while (lo < hi) { int mid = (lo + hi) >> 1; if (ngi[mid] < g) lo = mid + 1; else hi = mid; }
    int start = lo;
    hi = N_NODES;
    while (lo < hi) { int mid = (lo + hi) >> 1; if (ngi[mid] < g + 1) lo = mid + 1; else hi = mid; }
    int end = lo;

    const int c  = threadIdx.x & 31;
    const int rg = threadIdx.x >> 5;  // 0..7
    float local = 0.f;
    for (int i = start + rg; i < end; i += 8)
        local += g_agg1[(size_t)i * 32 + c];

    __shared__ float red[256];
    __shared__ float pooled[32];
    red[threadIdx.x] = local;
    __syncthreads();
    if (threadIdx.x < 32) {
        float s = red[threadIdx.x];
#pragma unroll
        for (int k = 1; k < 8; k++) s += red[threadIdx.x + 32 * k];
        float cnt = (float)((end - start) > 0 ? (end - start) : 1);
        pooled[threadIdx.x] = s / cnt;
    }
    __syncthreads();
    if (threadIdx.x < N_CLASSES) {
        float s = bd[threadIdx.x];
#pragma unroll
        for (int cc = 0; cc < D_H1; cc++)
            s += pooled[cc] * Wd[cc * N_CLASSES + threadIdx.x];
        out[(size_t)g * N_CLASSES + threadIdx.x] = s;
    }
}

// ---------------- launch ----------------
extern "C" void kernel_launch(void* const* d_in, const int* in_sizes, int n_in,
                              void* d_out, int out_size) {
    const float* x   = (const float*)d_in[0];
    const int*   ei  = (const int*)d_in[1];   // [2, E], int32
    const int*   ngi = (const int*)d_in[2];   // [N], int32, sorted
    const float* W0  = (const float*)d_in[3];
    const float* b0  = (const float*)d_in[4];
    const float* W1  = (const float*)d_in[5];
    const float* b1  = (const float*)d_in[6];
    const float* Wd  = (const float*)d_in[7];
    const float* bd  = (const float*)d_in[8];
    float*       out = (float*)d_out;

    const int T = 256;

    k_deg_init<<<(N_NODES + T - 1) / T, T>>>();
    k_deg_count<<<(N_EDGES + T - 1) / T, T>>>(ei);
    k_inv<<<(N_NODES + T - 1) / T, T>>>();

    k_gemm0<<<(N_NODES + 63) / 64, T>>>(x, W0);
    k_self0<<<(N_NODES * 16 + T - 1) / T, T>>>();
    k_scat0<<<(unsigned)(((long long)N_EDGES * 16 + T - 1) / T), T>>>(ei);
    k_relu0<<<(N_NODES * 16 + T - 1) / T, T>>>(b0);

    k_gemm1<<<(N_NODES + 127) / 128, T>>>(W1);
    k_self1<<<(N_NODES * 8 + T - 1) / T, T>>>();
    k_scat1<<<(unsigned)(((long long)N_EDGES * 8 + T - 1) / T), T>>>(ei);
    k_relu1<<<(N_NODES * 8 + T - 1) / T, T>>>(b1);

    k_pool<<<N_GRAPHS, T>>>(ngi, Wd, bd, out);
}

// round 4
// speedup vs baseline: 1.8015x; 1.8015x over previous
#include <cuda_runtime.h>
#include <cuda_bf16.h>

#define N_NODES   100000
#define N_EDGES   3200000
#define D_IN      128
#define D_H0      64
#define D_H1      32
#define N_GRAPHS  1024
#define N_CLASSES 16

#define SCAN_BLK  512
#define SCAN_NB   ((N_NODES + SCAN_BLK - 1) / SCAN_BLK)   // 196

// ---------------- scratch (static __device__, allocation-free) ----------------
__device__ int   g_cnt[N_NODES];            // in-degree (no self loop)
__device__ float g_inv[N_NODES];            // rsqrt(deg+1)
__device__ int   g_off[N_NODES];            // exclusive scan; mutated by fill -> end offsets
__device__ int   g_bsum[SCAN_NB];
__device__ int   g_boff[SCAN_NB];
__device__ int   g_csr[N_EDGES];            // source node per CSR slot
__device__ float g_hw0[N_NODES * D_H0];     // x @ W0
__device__ float g_h0 [N_NODES * D_H0];     // relu(agg0 + b0)
__device__ float g_hw1[N_NODES * D_H1];     // h0 @ W1
__device__ float g_h1 [N_NODES * D_H1];     // relu(agg1 + b1)

// ---------------- degree / inv ----------------
__global__ void k_cnt_zero() {
    int i = blockIdx.x * blockDim.x + threadIdx.x;
    if (i < N_NODES) g_cnt[i] = 0;
}
__global__ void k_cnt(const int* __restrict__ ei) {
    int e = blockIdx.x * blockDim.x + threadIdx.x;
    if (e < N_EDGES) atomicAdd(&g_cnt[ei[e]], 1);   // ei[0][e] = target
}
__global__ void k_inv() {
    int i = blockIdx.x * blockDim.x + threadIdx.x;
    if (i < N_NODES) g_inv[i] = rsqrtf((float)(g_cnt[i] + 1));
}

// ---------------- prefix sum (3-phase) ----------------
__global__ void k_scan1() {
    __shared__ int s[SCAN_BLK];
    int t = threadIdx.x;
    int i = blockIdx.x * SCAN_BLK + t;
    int v = (i < N_NODES) ? g_cnt[i] : 0;
    s[t] = v;
    __syncthreads();
    for (int off = 1; off < SCAN_BLK; off <<= 1) {
        int tmp = (t >= off) ? s[t - off] : 0;
        __syncthreads();
        s[t] += tmp;
        __syncthreads();
    }
    if (i < N_NODES) g_off[i] = s[t] - v;       // exclusive within block
    if (t == SCAN_BLK - 1) g_bsum[blockIdx.x] = s[t];
}
__global__ void k_scan2() {
    if (threadIdx.x == 0 && blockIdx.x == 0) {
        int run = 0;
        for (int b = 0; b < SCAN_NB; b++) { g_boff[b] = run; run += g_bsum[b]; }
    }
}
__global__ void k_scan3() {
    int i = blockIdx.x * SCAN_BLK + threadIdx.x;
    if (i < N_NODES) g_off[i] += g_boff[blockIdx.x];
}

// ---------------- CSR fill (mutates g_off -> end offsets) ----------------
__global__ void k_fill(const int* __restrict__ ei) {
    int e = blockIdx.x * blockDim.x + threadIdx.x;
    if (e < N_EDGES) {
        int r = ei[e];
        int c = ei[N_EDGES + e];
        int slot = atomicAdd(&g_off[r], 1);
        g_csr[slot] = c;
    }
}

// ---------------- GEMM0: hw0 = x[N,128] @ W0[128,64] ----------------
// 256 thr: rg = t>>3 (0..31), cols c0=(t&7)*8; thread rows rg+{0,32,64,96}.
__global__ __launch_bounds__(256) void k_gemm0(const float* __restrict__ x,
                                               const float* __restrict__ W0) {
    __shared__ float xs[128 * 36];   // 18 KB, padded stride 36
    __shared__ float ws[32 * 64];    //  8 KB
    const int t  = threadIdx.x;
    const int rg = t >> 3;
    const int c0 = (t & 7) * 8;
    const int rbase = blockIdx.x * 128;

    float acc[4][8];
#pragma unroll
    for (int m = 0; m < 4; m++)
#pragma unroll
        for (int j = 0; j < 8; j++) acc[m][j] = 0.f;

    for (int kc = 0; kc < 4; kc++) {
        // stage x chunk: 128 rows x 32 k
#pragma unroll
        for (int i = t; i < 1024; i += 256) {
            int row = i >> 3, kk = i & 7;
            int grow = rbase + row;
            float4 v = make_float4(0.f, 0.f, 0.f, 0.f);
            if (grow < N_NODES)
                v = *(const float4*)(x + (size_t)grow * D_IN + kc * 32 + kk * 4);
            *(float4*)(xs + row * 36 + kk * 4) = v;
        }
        // stage W chunk: 32 k x 64 cols
#pragma unroll
        for (int i = t; i < 512; i += 256)
            *(float4*)(ws + i * 4) = *(const float4*)(W0 + (size_t)kc * 32 * D_H0 + i * 4);
        __syncthreads();

#pragma unroll
        for (int k4 = 0; k4 < 8; k4++) {
            float4 xv[4];
#pragma unroll
            for (int m = 0; m < 4; m++)
                xv[m] = *(const float4*)(xs + (rg + 32 * m) * 36 + k4 * 4);
#pragma unroll
            for (int kk = 0; kk < 4; kk++) {
                float4 wa = *(const float4*)(ws + (k4 * 4 + kk) * 64 + c0);
                float4 wb = *(const float4*)(ws + (k4 * 4 + kk) * 64 + c0 + 4);
#pragma unroll
                for (int m = 0; m < 4; m++) {
                    float xb = (kk == 0) ? xv[m].x : (kk == 1) ? xv[m].y
                             : (kk == 2) ? xv[m].z : xv[m].w;
                    acc[m][0] += xb * wa.x; acc[m][1] += xb * wa.y;
                    acc[m][2] += xb * wa.z; acc[m][3] += xb * wa.w;
                    acc[m][4] += xb * wb.x; acc[m][5] += xb * wb.y;
                    acc[m][6] += xb * wb.z; acc[m][7] += xb * wb.w;
                }
            }
        }
        __syncthreads();
    }
#pragma unroll
    for (int m = 0; m < 4; m++) {
        int row = rbase + rg + 32 * m;
        if (row < N_NODES) {
            float* o = g_hw0 + (size_t)row * D_H0 + c0;
            *(float4*)(o)     = make_float4(acc[m][0], acc[m][1], acc[m][2], acc[m][3]);
            *(float4*)(o + 4) = make_float4(acc[m][4], acc[m][5], acc[m][6], acc[m][7]);
        }
    }
}

// ---------------- GEMM1: hw1 = h0[N,64] @ W1[64,32] ----------------
// 128 thr: rg = t>>2 (0..31), cols c0=(t&3)*8; rows rg+{0,32,64,96}.
__global__ __launch_bounds__(128) void k_gemm1(const float* __restrict__ W1) {
    __shared__ float xs[128 * 36];   // 18 KB
    __shared__ float ws[32 * 32];    //  4 KB
    const int t  = threadIdx.x;
    const int rg = t >> 2;
    const int c0 = (t & 3) * 8;
    const int rbase = blockIdx.x * 128;

    float acc[4][8];
#pragma unroll
    for (int m = 0; m < 4; m++)
#pragma unroll
        for (int j = 0; j < 8; j++) acc[m][j] = 0.f;

    for (int kc = 0; kc < 2; kc++) {
#pragma unroll
        for (int i = t; i < 1024; i += 128) {
            int row = i >> 3, kk = i & 7;
            int grow = rbase + row;
            float4 v = make_float4(0.f, 0.f, 0.f, 0.f);
            if (grow < N_NODES)
                v = *(const float4*)(g_h0 + (size_t)grow * D_H0 + kc * 32 + kk * 4);
            *(float4*)(xs + row * 36 + kk * 4) = v;
        }
#pragma unroll
        for (int i = t; i < 256; i += 128)
            *(float4*)(ws + i * 4) = *(const float4*)(W1 + (size_t)kc * 32 * D_H1 + i * 4);
        __syncthreads();

#pragma unroll
        for (int k4 = 0; k4 < 8; k4++) {
            float4 xv[4];
#pragma unroll
            for (int m = 0; m < 4; m++)
                xv[m] = *(const float4*)(xs + (rg + 32 * m) * 36 + k4 * 4);
#pragma unroll
            for (int kk = 0; kk < 4; kk++) {
                float4 wa = *(const float4*)(ws + (k4 * 4 + kk) * 32 + c0);
                float4 wb = *(const float4*)(ws + (k4 * 4 + kk) * 32 + c0 + 4);
#pragma unroll
                for (int m = 0; m < 4; m++) {
                    float xb = (kk == 0) ? xv[m].x : (kk == 1) ? xv[m].y
                             : (kk == 2) ? xv[m].z : xv[m].w;
                    acc[m][0] += xb * wa.x; acc[m][1] += xb * wa.y;
                    acc[m][2] += xb * wa.z; acc[m][3] += xb * wa.w;
                    acc[m][4] += xb * wb.x; acc[m][5] += xb * wb.y;
                    acc[m][6] += xb * wb.z; acc[m][7] += xb * wb.w;
                }
            }
        }
        __syncthreads();
    }
#pragma unroll
    for (int m = 0; m < 4; m++) {
        int row = rbase + rg + 32 * m;
        if (row < N_NODES) {
            float* o = g_hw1 + (size_t)row * D_H1 + c0;
            *(float4*)(o)     = make_float4(acc[m][0], acc[m][1], acc[m][2], acc[m][3]);
            *(float4*)(o + 4) = make_float4(acc[m][4], acc[m][5], acc[m][6], acc[m][7]);
        }
    }
}

// ---------------- gather L0: warp per node, fused self+bias+relu ----------------
__global__ void k_gather0(const float* __restrict__ b0) {
    int warp = (blockIdx.x * blockDim.x + threadIdx.x) >> 5;
    int lane = threadIdx.x & 31;
    if (warp >= N_NODES) return;
    const int node = warp;
    float inv_r = g_inv[node];
    int start = (node == 0) ? 0 : g_off[node - 1];
    int end = g_off[node];

    const float2* hw = (const float2*)g_hw0;
    float2 self = hw[(size_t)node * 32 + lane];
    float tx = inv_r * self.x, ty = inv_r * self.y;  // self-loop term (pre inv_r scale)

    for (int base = start; base < end; base += 32) {
        int idx = base + lane;
        int c = 0; float ic = 0.f;
        if (idx < end) { c = g_csr[idx]; ic = g_inv[c]; }
        int m = min(32, end - base);
        for (int j = 0; j < m; j++) {
            int   cc = __shfl_sync(0xffffffffu, c, j);
            float w  = __shfl_sync(0xffffffffu, ic, j);
            float2 v = hw[(size_t)cc * 32 + lane];
            tx += w * v.x; ty += w * v.y;
        }
    }
    float2 b = ((const float2*)b0)[lane];
    float2 o;
    o.x = fmaxf(inv_r * tx + b.x, 0.f);
    o.y = fmaxf(inv_r * ty + b.y, 0.f);
    ((float2*)g_h0)[(size_t)node * 32 + lane] = o;
}

// ---------------- gather L1: warp per node (32 cols -> 1 float/lane) ----------------
__global__ void k_gather1(const float* __restrict__ b1) {
    int warp = (blockIdx.x * blockDim.x + threadIdx.x) >> 5;
    int lane = threadIdx.x & 31;
    if (warp >= N_NODES) return;
    const int node = warp;
    float inv_r = g_inv[node];
    int start = (node == 0) ? 0 : g_off[node - 1];
    int end = g_off[node];

    float tsum = inv_r * g_hw1[(size_t)node * 32 + lane];

    for (int base = start; base < end; base += 32) {
        int idx = base + lane;
        int c = 0; float ic = 0.f;
        if (idx < end) { c = g_csr[idx]; ic = g_inv[c]; }
        int m = min(32, end - base);
        for (int j = 0; j < m; j++) {
            int   cc = __shfl_sync(0xffffffffu, c, j);
            float w  = __shfl_sync(0xffffffffu, ic, j);
            tsum += w * g_hw1[(size_t)cc * 32 + lane];
        }
    }
    g_h1[(size_t)node * 32 + lane] = fmaxf(inv_r * tsum + b1[lane], 0.f);
}

// ---------------- mean pool per graph + dense head ----------------
__global__ void k_pool(const int* __restrict__ ngi,
                       const float* __restrict__ Wd,
                       const float* __restrict__ bd,
                       float* __restrict__ out) {
    const int g = blockIdx.x;

    int lo = 0, hi = N_NODES;
    while (lo < hi) { int mid = (lo + hi) >> 1; if (ngi[mid] < g) lo = mid + 1; else hi = mid; }
    int start = lo;
    hi = N_NODES;
    while (lo < hi) { int mid = (lo + hi) >> 1; if (ngi[mid] < g + 1) lo = mid + 1; else hi = mid; }
    int end = lo;

    const int c  = threadIdx.x & 31;
    const int rg = threadIdx.x >> 5;  // 0..7
    float local = 0.f;
    for (int i = start + rg; i < end; i += 8)
        local += g_h1[(size_t)i * 32 + c];

    __shared__ float red[256];
    __shared__ float pooled[32];
    red[threadIdx.x] = local;
    __syncthreads();
    if (threadIdx.x < 32) {
        float s = red[threadIdx.x];
#pragma unroll
        for (int k = 1; k < 8; k++) s += red[threadIdx.x + 32 * k];
        float cnt = (float)((end - start) > 0 ? (end - start) : 1);
        pooled[threadIdx.x] = s / cnt;
    }
    __syncthreads();
    if (threadIdx.x < N_CLASSES) {
        float s = bd[threadIdx.x];
#pragma unroll
        for (int cc = 0; cc < D_H1; cc++)
            s += pooled[cc] * Wd[cc * N_CLASSES + threadIdx.x];
        out[(size_t)g * N_CLASSES + threadIdx.x] = s;
    }
}

// ---------------- launch ----------------
extern "C" void kernel_launch(void* const* d_in, const int* in_sizes, int n_in,
                              void* d_out, int out_size) {
    const float* x   = (const float*)d_in[0];
    const int*   ei  = (const int*)d_in[1];   // [2, E], int32
    const int*   ngi = (const int*)d_in[2];   // [N], int32, sorted
    const float* W0  = (const float*)d_in[3];
    const float* b0  = (const float*)d_in[4];
    const float* W1  = (const float*)d_in[5];
    const float* b1  = (const float*)d_in[6];
    const float* Wd  = (const float*)d_in[7];
    const float* bd  = (const float*)d_in[8];
    float*       out = (float*)d_out;

    const int T = 256;

    // degree + CSR build
    k_cnt_zero<<<(N_NODES + T - 1) / T, T>>>();
    k_cnt<<<(N_EDGES + T - 1) / T, T>>>(ei);
    k_inv<<<(N_NODES + T - 1) / T, T>>>();
    k_scan1<<<SCAN_NB, SCAN_BLK>>>();
    k_scan2<<<1, 32>>>();
    k_scan3<<<SCAN_NB, SCAN_BLK>>>();
    k_fill<<<(N_EDGES + T - 1) / T, T>>>(ei);

    // layer 0
    k_gemm0<<<(N_NODES + 127) / 128, 256>>>(x, W0);
    k_gather0<<<(N_NODES * 32 + T - 1) / T, T>>>(b0);

    // layer 1
    k_gemm1<<<(N_NODES + 127) / 128, 128>>>(W1);
    k_gather1<<<(N_NODES * 32 + T - 1) / T, T>>>(b1);

    // pool + head
    k_pool<<<N_GRAPHS, T>>>(ngi, Wd, bd, out);
}

// round 6
// speedup vs baseline: 2.0998x; 1.1656x over previous
#include <cuda_runtime.h>
#include <cuda_bf16.h>

#define N_NODES   100000
#define N_EDGES   3200000
#define D_IN      128
#define D_H0      64
#define D_H1      32
#define N_GRAPHS  1024
#define N_CLASSES 16

#define SCAN_BLK  512
#define SCAN_NB   ((N_NODES + SCAN_BLK - 1) / SCAN_BLK)   // 196

// ---------------- scratch (static __device__, allocation-free) ----------------
__device__ int   g_cnt[N_NODES];                 // in-degree (no self loop)
__device__ float g_inv[N_NODES];                 // rsqrt(deg+1)
__device__ int   g_off[N_NODES];                 // excl scan; mutated by fill -> end offsets
__device__ int   g_bsum[SCAN_NB];
__device__ int   g_boff[SCAN_NB];
__device__ int2  g_csr[N_EDGES];                 // (source node, bits(inv[source]))
__device__ __nv_bfloat16 g_hw0[N_NODES * D_H0];  // x @ W0   (bf16 payload)
__device__ float g_h0 [N_NODES * D_H0];          // relu(agg0 + b0), fp32
__device__ __nv_bfloat16 g_hw1[N_NODES * D_H1];  // h0 @ W1  (bf16 payload)
__device__ float g_h1 [N_NODES * D_H1];          // relu(agg1 + b1), fp32

// ---------------- degree ----------------
__global__ void k_cnt_zero() {
    int i = blockIdx.x * blockDim.x + threadIdx.x;
    if (i < N_NODES) g_cnt[i] = 0;
}
__global__ void k_cnt(const int* __restrict__ ei) {
    int e = blockIdx.x * blockDim.x + threadIdx.x;
    if (e < N_EDGES) atomicAdd(&g_cnt[ei[e]], 1);   // ei[0][e] = target
}

// ---------------- prefix sum (3-phase) + inv fused into phase 1 ----------------
__global__ void k_scan1() {
    __shared__ int s[SCAN_BLK];
    int t = threadIdx.x;
    int i = blockIdx.x * SCAN_BLK + t;
    int v = (i < N_NODES) ? g_cnt[i] : 0;
    if (i < N_NODES) g_inv[i] = rsqrtf((float)(v + 1));
    s[t] = v;
    __syncthreads();
    for (int off = 1; off < SCAN_BLK; off <<= 1) {
        int tmp = (t >= off) ? s[t - off] : 0;
        __syncthreads();
        s[t] += tmp;
        __syncthreads();
    }
    if (i < N_NODES) g_off[i] = s[t] - v;       // exclusive within block
    if (t == SCAN_BLK - 1) g_bsum[blockIdx.x] = s[t];
}
__global__ void k_scan2() {   // 1 warp, shfl scan over SCAN_NB block sums
    int lane = threadIdx.x;
    int run = 0;
    for (int b0 = 0; b0 < SCAN_NB; b0 += 32) {
        int i = b0 + lane;
        int v0 = (i < SCAN_NB) ? g_bsum[i] : 0;
        int v = v0;
#pragma unroll
        for (int off = 1; off < 32; off <<= 1) {
            int tmp = __shfl_up_sync(0xffffffffu, v, off);
            if (lane >= off) v += tmp;
        }
        if (i < SCAN_NB) g_boff[i] = run + v - v0;   // exclusive
        run += __shfl_sync(0xffffffffu, v, 31);
    }
}
__global__ void k_scan3() {
    int i = blockIdx.x * SCAN_BLK + threadIdx.x;
    if (i < N_NODES) g_off[i] += g_boff[blockIdx.x];
}

// ---------------- CSR fill: pack (col, inv[col]); mutates g_off -> end offsets --
__global__ void k_fill(const int* __restrict__ ei) {
    int e = blockIdx.x * blockDim.x + threadIdx.x;
    if (e < N_EDGES) {
        int r = ei[e];
        int c = ei[N_EDGES + e];
        float ic = g_inv[c];
        int slot = atomicAdd(&g_off[r], 1);
        g_csr[slot] = make_int2(c, __float_as_int(ic));
    }
}

// ---------------- GEMM0: hw0 = x[N,128] @ W0[128,64] -> bf16 ----------------
__global__ __launch_bounds__(256) void k_gemm0(const float* __restrict__ x,
                                               const float* __restrict__ W0) {
    __shared__ float xs[128 * 36];   // 18 KB, padded stride 36
    __shared__ float ws[32 * 64];    //  8 KB
    const int t  = threadIdx.x;
    const int rg = t >> 3;
    const int c0 = (t & 7) * 8;
    const int rbase = blockIdx.x * 128;

    float acc[4][8];
#pragma unroll
    for (int m = 0; m < 4; m++)
#pragma unroll
        for (int j = 0; j < 8; j++) acc[m][j] = 0.f;

    for (int kc = 0; kc < 4; kc++) {
#pragma unroll
        for (int i = t; i < 1024; i += 256) {
            int row = i >> 3, kk = i & 7;
            int grow = rbase + row;
            float4 v = make_float4(0.f, 0.f, 0.f, 0.f);
            if (grow < N_NODES)
                v = *(const float4*)(x + (size_t)grow * D_IN + kc * 32 + kk * 4);
            *(float4*)(xs + row * 36 + kk * 4) = v;
        }
#pragma unroll
        for (int i = t; i < 512; i += 256)
            *(float4*)(ws + i * 4) = *(const float4*)(W0 + (size_t)kc * 32 * D_H0 + i * 4);
        __syncthreads();

#pragma unroll
        for (int k4 = 0; k4 < 8; k4++) {
            float4 xv[4];
#pragma unroll
            for (int m = 0; m < 4; m++)
                xv[m] = *(const float4*)(xs + (rg + 32 * m) * 36 + k4 * 4);
#pragma unroll
            for (int kk = 0; kk < 4; kk++) {
                float4 wa = *(const float4*)(ws + (k4 * 4 + kk) * 64 + c0);
                float4 wb = *(const float4*)(ws + (k4 * 4 + kk) * 64 + c0 + 4);
#pragma unroll
                for (int m = 0; m < 4; m++) {
                    float xb = (kk == 0) ? xv[m].x : (kk == 1) ? xv[m].y
                             : (kk == 2) ? xv[m].z : xv[m].w;
                    acc[m][0] += xb * wa.x; acc[m][1] += xb * wa.y;
                    acc[m][2] += xb * wa.z; acc[m][3] += xb * wa.w;
                    acc[m][4] += xb * wb.x; acc[m][5] += xb * wb.y;
                    acc[m][6] += xb * wb.z; acc[m][7] += xb * wb.w;
                }
            }
        }
        __syncthreads();
    }
#pragma unroll
    for (int m = 0; m < 4; m++) {
        int row = rbase + rg + 32 * m;
        if (row < N_NODES) {
            union { uint4 u; __nv_bfloat162 h[4]; } pk;
#pragma unroll
            for (int p = 0; p < 4; p++)
                pk.h[p] = __floats2bfloat162_rn(acc[m][2 * p], acc[m][2 * p + 1]);
            *(uint4*)(g_hw0 + (size_t)row * D_H0 + c0) = pk.u;
        }
    }
}

// ---------------- GEMM1: hw1 = h0[N,64] @ W1[64,32] -> bf16 ----------------
__global__ __launch_bounds__(128) void k_gemm1(const float* __restrict__ W1) {
    __shared__ float xs[128 * 36];   // 18 KB
    __shared__ float ws[32 * 32];    //  4 KB
    const int t  = threadIdx.x;
    const int rg = t >> 2;
    const int c0 = (t & 3) * 8;
    const int rbase = blockIdx.x * 128;

    float acc[4][8];
#pragma unroll
    for (int m = 0; m < 4; m++)
#pragma unroll
        for (int j = 0; j < 8; j++) acc[m][j] = 0.f;

    for (int kc = 0; kc < 2; kc++) {
#pragma unroll
        for (int i = t; i < 1024; i += 128) {
            int row = i >> 3, kk = i & 7;
            int grow = rbase + row;
            float4 v = make_float4(0.f, 0.f, 0.f, 0.f);
            if (grow < N_NODES)
                v = *(const float4*)(g_h0 + (size_t)grow * D_H0 + kc * 32 + kk * 4);
            *(float4*)(xs + row * 36 + kk * 4) = v;
        }
#pragma unroll
        for (int i = t; i < 256; i += 128)
            *(float4*)(ws + i * 4) = *(const float4*)(W1 + (size_t)kc * 32 * D_H1 + i * 4);
        __syncthreads();

#pragma unroll
        for (int k4 = 0; k4 < 8; k4++) {
            float4 xv[4];
#pragma unroll
            for (int m = 0; m < 4; m++)
                xv[m] = *(const float4*)(xs + (rg + 32 * m) * 36 + k4 * 4);
#pragma unroll
            for (int kk = 0; kk < 4; kk++) {
                float4 wa = *(const float4*)(ws + (k4 * 4 + kk) * 32 + c0);
                float4 wb = *(const float4*)(ws + (k4 * 4 + kk) * 32 + c0 + 4);
#pragma unroll
                for (int m = 0; m < 4; m++) {
                    float xb = (kk == 0) ? xv[m].x : (kk == 1) ? xv[m].y
                             : (kk == 2) ? xv[m].z : xv[m].w;
                    acc[m][0] += xb * wa.x; acc[m][1] += xb * wa.y;
                    acc[m][2] += xb * wa.z; acc[m][3] += xb * wa.w;
                    acc[m][4] += xb * wb.x; acc[m][5] += xb * wb.y;
                    acc[m][6] += xb * wb.z; acc[m][7] += xb * wb.w;
                }
            }
        }
        __syncthreads();
    }
#pragma unroll
    for (int m = 0; m < 4; m++) {
        int row = rbase + rg + 32 * m;
        if (row < N_NODES) {
            union { uint4 u; __nv_bfloat162 h[4]; } pk;
#pragma unroll
            for (int p = 0; p < 4; p++)
                pk.h[p] = __floats2bfloat162_rn(acc[m][2 * p], acc[m][2 * p + 1]);
            *(uint4*)(g_hw1 + (size_t)row * D_H1 + c0) = pk.u;
        }
    }
}

// ---------------- gather L0: warp/node, bf16 payload, fused self+bias+relu ----
__global__ void k_gather0(const float* __restrict__ b0) {
    int warp = (blockIdx.x * blockDim.x + threadIdx.x) >> 5;
    int lane = threadIdx.x & 31;
    if (warp >= N_NODES) return;
    const int node = warp;
    float inv_r = g_inv[node];
    int start = (node == 0) ? 0 : g_off[node - 1];
    int end = g_off[node];

    const __nv_bfloat162* hw = (const __nv_bfloat162*)g_hw0;
    float2 self = __bfloat1622float2(hw[(size_t)node * 32 + lane]);
    float tx = inv_r * self.x, ty = inv_r * self.y;

    int base = start;
    for (; base + 32 <= end; base += 32) {
        int2 p = g_csr[base + lane];
        int c = p.x;
        float ic = __int_as_float(p.y);
#pragma unroll 8
        for (int j = 0; j < 32; j++) {
            int   cc = __shfl_sync(0xffffffffu, c, j);
            float w  = __shfl_sync(0xffffffffu, ic, j);
            float2 v = __bfloat1622float2(hw[(size_t)cc * 32 + lane]);
            tx += w * v.x; ty += w * v.y;
        }
    }
    int rem = end - base;
    if (rem > 0) {
        int c = 0; float ic = 0.f;
        if (lane < rem) {
            int2 p = g_csr[base + lane];
            c = p.x; ic = __int_as_float(p.y);
        }
        for (int j = 0; j < rem; j++) {
            int   cc = __shfl_sync(0xffffffffu, c, j);
            float w  = __shfl_sync(0xffffffffu, ic, j);
            float2 v = __bfloat1622float2(hw[(size_t)cc * 32 + lane]);
            tx += w * v.x; ty += w * v.y;
        }
    }
    float2 b = ((const float2*)b0)[lane];
    float2 o;
    o.x = fmaxf(inv_r * tx + b.x, 0.f);
    o.y = fmaxf(inv_r * ty + b.y, 0.f);
    ((float2*)g_h0)[(size_t)node * 32 + lane] = o;
}

// ---------------- gather L1: warp/node, bf16 payload ----------------
__global__ void k_gather1(const float* __restrict__ b1) {
    int warp = (blockIdx.x * blockDim.x + threadIdx.x) >> 5;
    int lane = threadIdx.x & 31;
    if (warp >= N_NODES) return;
    const int node = warp;
    float inv_r = g_inv[node];
    int start = (node == 0) ? 0 : g_off[node - 1];
    int end = g_off[node];

    float tsum = inv_r * __bfloat162float(g_hw1[(size_t)node * 32 + lane]);

    int base = start;
    for (; base + 32 <= end; base += 32) {
        int2 p = g_csr[base + lane];
        int c = p.x;
        float ic = __int_as_float(p.y);
#pragma unroll 8
        for (int j = 0; j < 32; j++) {
            int   cc = __shfl_sync(0xffffffffu, c, j);
            float w  = __shfl_sync(0xffffffffu, ic, j);
            tsum += w * __bfloat162float(g_hw1[(size_t)cc * 32 + lane]);
        }
    }
    int rem = end - base;
    if (rem > 0) {
        int c = 0; float ic = 0.f;
        if (lane < rem) {
            int2 p = g_csr[base + lane];
            c = p.x; ic = __int_as_float(p.y);
        }
        for (int j = 0; j < rem; j++) {
            int   cc = __shfl_sync(0xffffffffu, c, j);
            float w  = __shfl_sync(0xffffffffu, ic, j);
            tsum += w * __bfloat162float(g_hw1[(size_t)cc * 32 + lane]);
        }
    }
    g_h1[(size_t)node * 32 + lane] = fmaxf(inv_r * tsum + b1[lane], 0.f);
}

// ---------------- mean pool per graph + dense head ----------------
__global__ void k_pool(const int* __restrict__ ngi,
                       const float* __restrict__ Wd,
                       const float* __restrict__ bd,
                       float* __restrict__ out) {
    const int g = blockIdx.x;

    int lo = 0, hi = N_NODES;
    while (lo < hi) { int mid = (lo + hi) >> 1; if (ngi[mid] < g) lo = mid + 1; else hi = mid; }
    int start = lo;
    hi = N_NODES;
    while (lo < hi) { int mid = (lo + hi) >> 1; if (ngi[mid] < g + 1) lo = mid + 1; else hi = mid; }
    int end = lo;

    const int c  = threadIdx.x & 31;
    const int rg = threadIdx.x >> 5;  // 0..7
    float local = 0.f;
    for (int i = start + rg; i < end; i += 8)
        local += g_h1[(size_t)i * 32 + c];

    __shared__ float red[256];
    __shared__ float pooled[32];
    red[threadIdx.x] = local;
    __syncthreads();
    if (threadIdx.x < 32) {
        float s = red[threadIdx.x];
#pragma unroll
        for (int k = 1; k < 8; k++) s += red[threadIdx.x + 32 * k];
        float cnt = (float)((end - start) > 0 ? (end - start) : 1);
        pooled[threadIdx.x] = s / cnt;
    }
    __syncthreads();
    if (threadIdx.x < N_CLASSES) {
        float s = bd[threadIdx.x];
#pragma unroll
        for (int cc = 0; cc < D_H1; cc++)
            s += pooled[cc] * Wd[cc * N_CLASSES + threadIdx.x];
        out[(size_t)g * N_CLASSES + threadIdx.x] = s;
    }
}

// ---------------- launch ----------------
extern "C" void kernel_launch(void* const* d_in, const int* in_sizes, int n_in,
                              void* d_out, int out_size) {
    const float* x   = (const float*)d_in[0];
    const int*   ei  = (const int*)d_in[1];   // [2, E], int32
    const int*   ngi = (const int*)d_in[2];   // [N], int32, sorted
    const float* W0  = (const float*)d_in[3];
    const float* b0  = (const float*)d_in[4];
    const float* W1  = (const float*)d_in[5];
    const float* b1  = (const float*)d_in[6];
    const float* Wd  = (const float*)d_in[7];
    const float* bd  = (const float*)d_in[8];
    float*       out = (float*)d_out;

    const int T = 256;

    // degree + CSR build
    k_cnt_zero<<<(N_NODES + T - 1) / T, T>>>();
    k_cnt<<<(N_EDGES + T - 1) / T, T>>>(ei);
    k_scan1<<<SCAN_NB, SCAN_BLK>>>();
    k_scan2<<<1, 32>>>();
    k_scan3<<<SCAN_NB, SCAN_BLK>>>();
    k_fill<<<(N_EDGES + T - 1) / T, T>>>(ei);

    // layer 0
    k_gemm0<<<(N_NODES + 127) / 128, 256>>>(x, W0);
    k_gather0<<<(N_NODES * 32 + T - 1) / T, T>>>(b0);

    // layer 1
    k_gemm1<<<(N_NODES + 127) / 128, 128>>>(W1);
    k_gather1<<<(N_NODES * 32 + T - 1) / T, T>>>(b1);

    // pool + head
    k_pool<<<N_GRAPHS, T>>>(ngi, Wd, bd, out);
}

// round 7
// speedup vs baseline: 2.1782x; 1.0373x over previous
#include <cuda_runtime.h>
#include <cuda_bf16.h>

#define N_NODES   100000
#define N_EDGES   3200000
#define D_IN      128
#define D_H0      64
#define D_H1      32
#define N_GRAPHS  1024
#define N_CLASSES 16

#define SCAN_BLK  512
#define SCAN_NB   ((N_NODES + SCAN_BLK - 1) / SCAN_BLK)   // 196

// ---------------- scratch (static __device__, allocation-free) ----------------
__device__ int   g_cnt[N_NODES];                 // in-degree (no self loop)
__device__ float g_inv[N_NODES];                 // rsqrt(deg+1)
__device__ int   g_off[N_NODES];                 // excl scan; mutated by fill -> end offsets
__device__ int   g_bsum[SCAN_NB];
__device__ int   g_boff[SCAN_NB];
__device__ int2  g_csr[N_EDGES];                 // (source node, bits(inv[source]))
__device__ __nv_bfloat16 g_hw0[N_NODES * D_H0];  // x @ W0   (bf16 payload)
__device__ __nv_bfloat16 g_h0 [N_NODES * D_H0];  // relu(agg0 + b0)  (bf16, feeds gemm1 only)
__device__ __nv_bfloat16 g_hw1[N_NODES * D_H1];  // h0 @ W1  (bf16 payload)
__device__ float g_pool[N_GRAPHS * D_H1];        // per-graph sums (fp32 red.add)

// ---------------- zero counters + pool sums ----------------
__global__ void k_zero() {
    int i = blockIdx.x * blockDim.x + threadIdx.x;
    if (i < N_NODES) g_cnt[i] = 0;
    if (i < N_GRAPHS * D_H1) g_pool[i] = 0.f;
}
__global__ void k_cnt(const int* __restrict__ ei) {
    int e = blockIdx.x * blockDim.x + threadIdx.x;
    if (e < N_EDGES) atomicAdd(&g_cnt[ei[e]], 1);   // ei[0][e] = target
}

// ---------------- prefix sum (3-phase) + inv fused into phase 1 ----------------
__global__ void k_scan1() {
    __shared__ int s[SCAN_BLK];
    int t = threadIdx.x;
    int i = blockIdx.x * SCAN_BLK + t;
    int v = (i < N_NODES) ? g_cnt[i] : 0;
    if (i < N_NODES) g_inv[i] = rsqrtf((float)(v + 1));
    s[t] = v;
    __syncthreads();
    for (int off = 1; off < SCAN_BLK; off <<= 1) {
        int tmp = (t >= off) ? s[t - off] : 0;
        __syncthreads();
        s[t] += tmp;
        __syncthreads();
    }
    if (i < N_NODES) g_off[i] = s[t] - v;       // exclusive within block
    if (t == SCAN_BLK - 1) g_bsum[blockIdx.x] = s[t];
}
__global__ void k_scan2() {   // 1 warp, shfl scan over SCAN_NB block sums
    int lane = threadIdx.x;
    int run = 0;
    for (int b0 = 0; b0 < SCAN_NB; b0 += 32) {
        int i = b0 + lane;
        int v0 = (i < SCAN_NB) ? g_bsum[i] : 0;
        int v = v0;
#pragma unroll
        for (int off = 1; off < 32; off <<= 1) {
            int tmp = __shfl_up_sync(0xffffffffu, v, off);
            if (lane >= off) v += tmp;
        }
        if (i < SCAN_NB) g_boff[i] = run + v - v0;   // exclusive
        run += __shfl_sync(0xffffffffu, v, 31);
    }
}
__global__ void k_scan3() {
    int i = blockIdx.x * SCAN_BLK + threadIdx.x;
    if (i < N_NODES) g_off[i] += g_boff[blockIdx.x];
}

// ---------------- CSR fill: pack (col, inv[col]); mutates g_off -> end offsets --
__global__ void k_fill(const int* __restrict__ ei) {
    int e = blockIdx.x * blockDim.x + threadIdx.x;
    if (e < N_EDGES) {
        int r = ei[e];
        int c = ei[N_EDGES + e];
        float ic = g_inv[c];
        int slot = atomicAdd(&g_off[r], 1);
        g_csr[slot] = make_int2(c, __float_as_int(ic));
    }
}

// ---------------- GEMM0: hw0 = x[N,128] @ W0[128,64] -> bf16 ----------------
__global__ __launch_bounds__(256) void k_gemm0(const float* __restrict__ x,
                                               const float* __restrict__ W0) {
    __shared__ float xs[128 * 36];   // 18 KB, padded stride 36
    __shared__ float ws[32 * 64];    //  8 KB
    const int t  = threadIdx.x;
    const int rg = t >> 3;
    const int c0 = (t & 7) * 8;
    const int rbase = blockIdx.x * 128;

    float acc[4][8];
#pragma unroll
    for (int m = 0; m < 4; m++)
#pragma unroll
        for (int j = 0; j < 8; j++) acc[m][j] = 0.f;

    for (int kc = 0; kc < 4; kc++) {
#pragma unroll
        for (int i = t; i < 1024; i += 256) {
            int row = i >> 3, kk = i & 7;
            int grow = rbase + row;
            float4 v = make_float4(0.f, 0.f, 0.f, 0.f);
            if (grow < N_NODES)
                v = *(const float4*)(x + (size_t)grow * D_IN + kc * 32 + kk * 4);
            *(float4*)(xs + row * 36 + kk * 4) = v;
        }
#pragma unroll
        for (int i = t; i < 512; i += 256)
            *(float4*)(ws + i * 4) = *(const float4*)(W0 + (size_t)kc * 32 * D_H0 + i * 4);
        __syncthreads();

#pragma unroll
        for (int k4 = 0; k4 < 8; k4++) {
            float4 xv[4];
#pragma unroll
            for (int m = 0; m < 4; m++)
                xv[m] = *(const float4*)(xs + (rg + 32 * m) * 36 + k4 * 4);
#pragma unroll
            for (int kk = 0; kk < 4; kk++) {
                float4 wa = *(const float4*)(ws + (k4 * 4 + kk) * 64 + c0);
                float4 wb = *(const float4*)(ws + (k4 * 4 + kk) * 64 + c0 + 4);
#pragma unroll
                for (int m = 0; m < 4; m++) {
                    float xb = (kk == 0) ? xv[m].x : (kk == 1) ? xv[m].y
                             : (kk == 2) ? xv[m].z : xv[m].w;
                    acc[m][0] += xb * wa.x; acc[m][1] += xb * wa.y;
                    acc[m][2] += xb * wa.z; acc[m][3] += xb * wa.w;
                    acc[m][4] += xb * wb.x; acc[m][5] += xb * wb.y;
                    acc[m][6] += xb * wb.z; acc[m][7] += xb * wb.w;
                }
            }
        }
        __syncthreads();
    }
#pragma unroll
    for (int m = 0; m < 4; m++) {
        int row = rbase + rg + 32 * m;
        if (row < N_NODES) {
            union { uint4 u; __nv_bfloat162 h[4]; } pk;
#pragma unroll
            for (int p = 0; p < 4; p++)
                pk.h[p] = __floats2bfloat162_rn(acc[m][2 * p], acc[m][2 * p + 1]);
            *(uint4*)(g_hw0 + (size_t)row * D_H0 + c0) = pk.u;
        }
    }
}

// ---------------- GEMM1: hw1 = h0[N,64](bf16) @ W1[64,32] -> bf16 ----------------
__global__ __launch_bounds__(128) void k_gemm1(const float* __restrict__ W1) {
    __shared__ float xs[128 * 36];   // 18 KB
    __shared__ float ws[32 * 32];    //  4 KB
    const int t  = threadIdx.x;
    const int rg = t >> 2;
    const int c0 = (t & 3) * 8;
    const int rbase = blockIdx.x * 128;

    float acc[4][8];
#pragma unroll
    for (int m = 0; m < 4; m++)
#pragma unroll
        for (int j = 0; j < 8; j++) acc[m][j] = 0.f;

    for (int kc = 0; kc < 2; kc++) {
        // stage h0 chunk (bf16 -> fp32): 128 rows x 32 k; 8 bf16 per thread-iter
#pragma unroll
        for (int i = t; i < 512; i += 128) {
            int row = i >> 2, kk = i & 3;
            int grow = rbase + row;
            uint4 raw = make_uint4(0, 0, 0, 0);
            if (grow < N_NODES)
                raw = *(const uint4*)(g_h0 + (size_t)grow * D_H0 + kc * 32 + kk * 8);
            const __nv_bfloat162* hp = (const __nv_bfloat162*)&raw;
            float2 f0 = __bfloat1622float2(hp[0]);
            float2 f1 = __bfloat1622float2(hp[1]);
            float2 f2 = __bfloat1622float2(hp[2]);
            float2 f3 = __bfloat1622float2(hp[3]);
            *(float4*)(xs + row * 36 + kk * 8)     = make_float4(f0.x, f0.y, f1.x, f1.y);
            *(float4*)(xs + row * 36 + kk * 8 + 4) = make_float4(f2.x, f2.y, f3.x, f3.y);
        }
#pragma unroll
        for (int i = t; i < 256; i += 128)
            *(float4*)(ws + i * 4) = *(const float4*)(W1 + (size_t)kc * 32 * D_H1 + i * 4);
        __syncthreads();

#pragma unroll
        for (int k4 = 0; k4 < 8; k4++) {
            float4 xv[4];
#pragma unroll
            for (int m = 0; m < 4; m++)
                xv[m] = *(const float4*)(xs + (rg + 32 * m) * 36 + k4 * 4);
#pragma unroll
            for (int kk = 0; kk < 4; kk++) {
                float4 wa = *(const float4*)(ws + (k4 * 4 + kk) * 32 + c0);
                float4 wb = *(const float4*)(ws + (k4 * 4 + kk) * 32 + c0 + 4);
#pragma unroll
                for (int m = 0; m < 4; m++) {
                    float xb = (kk == 0) ? xv[m].x : (kk == 1) ? xv[m].y
                             : (kk == 2) ? xv[m].z : xv[m].w;
                    acc[m][0] += xb * wa.x; acc[m][1] += xb * wa.y;
                    acc[m][2] += xb * wa.z; acc[m][3] += xb * wa.w;
                    acc[m][4] += xb * wb.x; acc[m][5] += xb * wb.y;
                    acc[m][6] += xb * wb.z; acc[m][7] += xb * wb.w;
                }
            }
        }
        __syncthreads();
    }
#pragma unroll
    for (int m = 0; m < 4; m++) {
        int row = rbase + rg + 32 * m;
        if (row < N_NODES) {
            union { uint4 u; __nv_bfloat162 h[4]; } pk;
#pragma unroll
            for (int p = 0; p < 4; p++)
                pk.h[p] = __floats2bfloat162_rn(acc[m][2 * p], acc[m][2 * p + 1]);
            *(uint4*)(g_hw1 + (size_t)row * D_H1 + c0) = pk.u;
        }
    }
}

// ---------------- gather L0: warp/node, uniform CSR loads, fused bias+relu ----
__global__ void k_gather0(const float* __restrict__ b0) {
    int warp = (blockIdx.x * blockDim.x + threadIdx.x) >> 5;
    int lane = threadIdx.x & 31;
    if (warp >= N_NODES) return;
    const int node = warp;
    float inv_r = g_inv[node];
    int start = (node == 0) ? 0 : g_off[node - 1];
    int end = g_off[node];

    const __nv_bfloat162* hw = (const __nv_bfloat162*)g_hw0;
    float2 self = __bfloat1622float2(hw[(size_t)node * 32 + lane]);
    float tx = inv_r * self.x, ty = inv_r * self.y;

#pragma unroll 4
    for (int idx = start; idx < end; idx++) {
        int2 p = g_csr[idx];               // warp-uniform -> L1 broadcast
        float w = __int_as_float(p.y);
        float2 v = __bfloat1622float2(hw[(size_t)p.x * 32 + lane]);
        tx += w * v.x; ty += w * v.y;
    }

    float2 b = ((const float2*)b0)[lane];
    float ox = fmaxf(inv_r * tx + b.x, 0.f);
    float oy = fmaxf(inv_r * ty + b.y, 0.f);
    ((__nv_bfloat162*)g_h0)[(size_t)node * 32 + lane] = __floats2bfloat162_rn(ox, oy);
}

// ---------------- gather L1: warp/node; h1 folded straight into pool sums ------
__global__ void k_gather1(const int* __restrict__ ngi, const float* __restrict__ b1) {
    int warp = (blockIdx.x * blockDim.x + threadIdx.x) >> 5;
    int lane = threadIdx.x & 31;
    if (warp >= N_NODES) return;
    const int node = warp;
    float inv_r = g_inv[node];
    int start = (node == 0) ? 0 : g_off[node - 1];
    int end = g_off[node];

    float tsum = inv_r * __bfloat162float(g_hw1[(size_t)node * 32 + lane]);

#pragma unroll 4
    for (int idx = start; idx < end; idx++) {
        int2 p = g_csr[idx];               // warp-uniform -> L1 broadcast
        float w = __int_as_float(p.y);
        tsum += w * __bfloat162float(g_hw1[(size_t)p.x * 32 + lane]);
    }

    float h1 = fmaxf(inv_r * tsum + b1[lane], 0.f);
    int g = ngi[node];
    float* dst = g_pool + (size_t)g * D_H1 + lane;
    asm volatile("red.global.add.f32 [%0], %1;" :: "l"(dst), "f"(h1) : "memory");
}

// ---------------- per-graph mean + dense head ----------------
__global__ void k_head(const int* __restrict__ ngi,
                       const float* __restrict__ Wd,
                       const float* __restrict__ bd,
                       float* __restrict__ out) {
    const int g = blockIdx.x;
    const int lane = threadIdx.x;     // 32 threads

    int lo = 0, hi = N_NODES;
    while (lo < hi) { int mid = (lo + hi) >> 1; if (ngi[mid] < g) lo = mid + 1; else hi = mid; }
    int start = lo;
    hi = N_NODES;
    while (lo < hi) { int mid = (lo + hi) >> 1; if (ngi[mid] < g + 1) lo = mid + 1; else hi = mid; }
    int end = lo;

    float cnt = (float)((end - start) > 0 ? (end - start) : 1);
    __shared__ float ps[D_H1];
    ps[lane] = g_pool[(size_t)g * D_H1 + lane] / cnt;
    __syncwarp();

    if (lane < N_CLASSES) {
        float s = bd[lane];
#pragma unroll
        for (int c = 0; c < D_H1; c++)
            s += ps[c] * Wd[c * N_CLASSES + lane];
        out[(size_t)g * N_CLASSES + lane] = s;
    }
}

// ---------------- launch ----------------
extern "C" void kernel_launch(void* const* d_in, const int* in_sizes, int n_in,
                              void* d_out, int out_size) {
    const float* x   = (const float*)d_in[0];
    const int*   ei  = (const int*)d_in[1];   // [2, E], int32
    const int*   ngi = (const int*)d_in[2];   // [N], int32, sorted
    const float* W0  = (const float*)d_in[3];
    const float* b0  = (const float*)d_in[4];
    const float* W1  = (const float*)d_in[5];
    const float* b1  = (const float*)d_in[6];
    const float* Wd  = (const float*)d_in[7];
    const float* bd  = (const float*)d_in[8];
    float*       out = (float*)d_out;

    const int T = 256;

    // zero + degree + CSR build
    k_zero<<<(N_NODES + T - 1) / T, T>>>();
    k_cnt<<<(N_EDGES + T - 1) / T, T>>>(ei);
    k_scan1<<<SCAN_NB, SCAN_BLK>>>();
    k_scan2<<<1, 32>>>();
    k_scan3<<<SCAN_NB, SCAN_BLK>>>();
    k_fill<<<(N_EDGES + T - 1) / T, T>>>(ei);

    // layer 0
    k_gemm0<<<(N_NODES + 127) / 128, 256>>>(x, W0);
    k_gather0<<<(N_NODES * 32 + T - 1) / T, T>>>(b0);

    // layer 1
    k_gemm1<<<(N_NODES + 127) / 128, 128>>>(W1);
    k_gather1<<<(N_NODES * 32 + T - 1) / T, T>>>(ngi, b1);

    // pooled head
    k_head<<<N_GRAPHS, 32>>>(ngi, Wd, bd, out);
}

// round 8
// speedup vs baseline: 2.3085x; 1.0598x over previous
#include <cuda_runtime.h>
#include <cuda_bf16.h>

#define N_NODES   100000
#define N_EDGES   3200000
#define D_IN      128
#define D_H0      64
#define D_H1      32
#define N_GRAPHS  1024
#define N_CLASSES 16

#define SCAN_BLK  512
#define SCAN_NB   ((N_NODES + SCAN_BLK - 1) / SCAN_BLK)   // 196

// ---------------- scratch (static __device__, allocation-free) ----------------
// NOTE: g_cnt and g_pool must be ZERO on entry to kernel_launch. They are
// zero-initialized at module load (first call), and k_head re-zeros them at the
// end of every call, so every graph replay sees the same pre-state.
__device__ int   g_cnt[N_NODES];                 // in-degree (no self loop)
__device__ float g_inv[N_NODES];                 // rsqrt(deg+1)
__device__ int   g_off[N_NODES];                 // excl scan; mutated by fill -> end offsets
__device__ int   g_bsum[SCAN_NB];
__device__ int2  g_csr[N_EDGES];                 // (source node, bits(inv[source]))
__device__ __nv_bfloat16 g_hw0[N_NODES * D_H0];  // x @ W0   (bf16 payload)
__device__ __nv_bfloat16 g_h0 [N_NODES * D_H0];  // relu(agg0 + b0)  (bf16, feeds gemm1 only)
__device__ __nv_bfloat16 g_hw1[N_NODES * D_H1];  // h0 @ W1  (bf16 payload)
__device__ float g_pool[N_GRAPHS * D_H1];        // per-graph sums (fp32 red.add)

// ---------------- degree (2 edges / thread) ----------------
__global__ void k_cnt(const int* __restrict__ ei) {
    int e2 = blockIdx.x * blockDim.x + threadIdx.x;
    if (e2 < N_EDGES / 2) {
        int2 r = ((const int2*)ei)[e2];
        atomicAdd(&g_cnt[r.x], 1);
        atomicAdd(&g_cnt[r.y], 1);
    }
}

// ---------------- scan phase 1: per-block scan + inv ----------------
__global__ void k_scan1() {
    __shared__ int s[SCAN_BLK];
    int t = threadIdx.x;
    int i = blockIdx.x * SCAN_BLK + t;
    int v = (i < N_NODES) ? g_cnt[i] : 0;
    if (i < N_NODES) g_inv[i] = rsqrtf((float)(v + 1));
    s[t] = v;
    __syncthreads();
    for (int off = 1; off < SCAN_BLK; off <<= 1) {
        int tmp = (t >= off) ? s[t - off] : 0;
        __syncthreads();
        s[t] += tmp;
        __syncthreads();
    }
    if (i < N_NODES) g_off[i] = s[t] - v;       // exclusive within block
    if (t == SCAN_BLK - 1) g_bsum[blockIdx.x] = s[t];
}

// ---------------- scan phase 2+3 fused: each block sums its own prefix -------
__global__ void k_scan23() {
    __shared__ int s_pre;
    const int bid = blockIdx.x;
    if (threadIdx.x < 32) {
        int lane = threadIdx.x;
        int sum = 0;
        for (int b = lane; b < bid; b += 32) sum += g_bsum[b];
#pragma unroll
        for (int off = 16; off; off >>= 1) sum += __shfl_xor_sync(0xffffffffu, sum, off);
        if (lane == 0) s_pre = sum;
    }
    __syncthreads();
    int i = bid * SCAN_BLK + threadIdx.x;
    if (i < N_NODES) g_off[i] += s_pre;
}

// ---------------- CSR fill (2 edges / thread); mutates g_off -> end offsets --
__global__ void k_fill(const int* __restrict__ ei) {
    int e2 = blockIdx.x * blockDim.x + threadIdx.x;
    if (e2 < N_EDGES / 2) {
        int2 r = ((const int2*)ei)[e2];
        int2 c = ((const int2*)(ei + N_EDGES))[e2];
        float ic0 = g_inv[c.x];
        float ic1 = g_inv[c.y];
        int s0 = atomicAdd(&g_off[r.x], 1);
        g_csr[s0] = make_int2(c.x, __float_as_int(ic0));
        int s1 = atomicAdd(&g_off[r.y], 1);
        g_csr[s1] = make_int2(c.y, __float_as_int(ic1));
    }
}

// ---------------- GEMM0: hw0 = x[N,128] @ W0[128,64] -> bf16 ----------------
__global__ __launch_bounds__(256) void k_gemm0(const float* __restrict__ x,
                                               const float* __restrict__ W0) {
    __shared__ float xs[128 * 36];   // 18 KB, padded stride 36
    __shared__ float ws[32 * 64];    //  8 KB
    const int t  = threadIdx.x;
    const int rg = t >> 3;
    const int c0 = (t & 7) * 8;
    const int rbase = blockIdx.x * 128;

    float acc[4][8];
#pragma unroll
    for (int m = 0; m < 4; m++)
#pragma unroll
        for (int j = 0; j < 8; j++) acc[m][j] = 0.f;

    for (int kc = 0; kc < 4; kc++) {
#pragma unroll
        for (int i = t; i < 1024; i += 256) {
            int row = i >> 3, kk = i & 7;
            int grow = rbase + row;
            float4 v = make_float4(0.f, 0.f, 0.f, 0.f);
            if (grow < N_NODES)
                v = *(const float4*)(x + (size_t)grow * D_IN + kc * 32 + kk * 4);
            *(float4*)(xs + row * 36 + kk * 4) = v;
        }
#pragma unroll
        for (int i = t; i < 512; i += 256)
            *(float4*)(ws + i * 4) = *(const float4*)(W0 + (size_t)kc * 32 * D_H0 + i * 4);
        __syncthreads();

#pragma unroll
        for (int k4 = 0; k4 < 8; k4++) {
            float4 xv[4];
#pragma unroll
            for (int m = 0; m < 4; m++)
                xv[m] = *(const float4*)(xs + (rg + 32 * m) * 36 + k4 * 4);
#pragma unroll
            for (int kk = 0; kk < 4; kk++) {
                float4 wa = *(const float4*)(ws + (k4 * 4 + kk) * 64 + c0);
                float4 wb = *(const float4*)(ws + (k4 * 4 + kk) * 64 + c0 + 4);
#pragma unroll
                for (int m = 0; m < 4; m++) {
                    float xb = (kk == 0) ? xv[m].x : (kk == 1) ? xv[m].y
                             : (kk == 2) ? xv[m].z : xv[m].w;
                    acc[m][0] += xb * wa.x; acc[m][1] += xb * wa.y;
                    acc[m][2] += xb * wa.z; acc[m][3] += xb * wa.w;
                    acc[m][4] += xb * wb.x; acc[m][5] += xb * wb.y;
                    acc[m][6] += xb * wb.z; acc[m][7] += xb * wb.w;
                }
            }
        }
        __syncthreads();
    }
#pragma unroll
    for (int m = 0; m < 4; m++) {
        int row = rbase + rg + 32 * m;
        if (row < N_NODES) {
            union { uint4 u; __nv_bfloat162 h[4]; } pk;
#pragma unroll
            for (int p = 0; p < 4; p++)
                pk.h[p] = __floats2bfloat162_rn(acc[m][2 * p], acc[m][2 * p + 1]);
            *(uint4*)(g_hw0 + (size_t)row * D_H0 + c0) = pk.u;
        }
    }
}

// ---------------- GEMM1: hw1 = h0[N,64](bf16) @ W1[64,32] -> bf16 ----------------
__global__ __launch_bounds__(128) void k_gemm1(const float* __restrict__ W1) {
    __shared__ float xs[128 * 36];   // 18 KB
    __shared__ float ws[32 * 32];    //  4 KB
    const int t  = threadIdx.x;
    const int rg = t >> 2;
    const int c0 = (t & 3) * 8;
    const int rbase = blockIdx.x * 128;

    float acc[4][8];
#pragma unroll
    for (int m = 0; m < 4; m++)
#pragma unroll
        for (int j = 0; j < 8; j++) acc[m][j] = 0.f;

    for (int kc = 0; kc < 2; kc++) {
#pragma unroll
        for (int i = t; i < 512; i += 128) {
            int row = i >> 2, kk = i & 3;
            int grow = rbase + row;
            uint4 raw = make_uint4(0, 0, 0, 0);
            if (grow < N_NODES)
                raw = *(const uint4*)(g_h0 + (size_t)grow * D_H0 + kc * 32 + kk * 8);
            const __nv_bfloat162* hp = (const __nv_bfloat162*)&raw;
            float2 f0 = __bfloat1622float2(hp[0]);
            float2 f1 = __bfloat1622float2(hp[1]);
            float2 f2 = __bfloat1622float2(hp[2]);
            float2 f3 = __bfloat1622float2(hp[3]);
            *(float4*)(xs + row * 36 + kk * 8)     = make_float4(f0.x, f0.y, f1.x, f1.y);
            *(float4*)(xs + row * 36 + kk * 8 + 4) = make_float4(f2.x, f2.y, f3.x, f3.y);
        }
#pragma unroll
        for (int i = t; i < 256; i += 128)
            *(float4*)(ws + i * 4) = *(const float4*)(W1 + (size_t)kc * 32 * D_H1 + i * 4);
        __syncthreads();

#pragma unroll
        for (int k4 = 0; k4 < 8; k4++) {
            float4 xv[4];
#pragma unroll
            for (int m = 0; m < 4; m++)
                xv[m] = *(const float4*)(xs + (rg + 32 * m) * 36 + k4 * 4);
#pragma unroll
            for (int kk = 0; kk < 4; kk++) {
                float4 wa = *(const float4*)(ws + (k4 * 4 + kk) * 32 + c0);
                float4 wb = *(const float4*)(ws + (k4 * 4 + kk) * 32 + c0 + 4);
#pragma unroll
                for (int m = 0; m < 4; m++) {
                    float xb = (kk == 0) ? xv[m].x : (kk == 1) ? xv[m].y
                             : (kk == 2) ? xv[m].z : xv[m].w;
                    acc[m][0] += xb * wa.x; acc[m][1] += xb * wa.y;
                    acc[m][2] += xb * wa.z; acc[m][3] += xb * wa.w;
                    acc[m][4] += xb * wb.x; acc[m][5] += xb * wb.y;
                    acc[m][6] += xb * wb.z; acc[m][7] += xb * wb.w;
                }
            }
        }
        __syncthreads();
    }
#pragma unroll
    for (int m = 0; m < 4; m++) {
        int row = rbase + rg + 32 * m;
        if (row < N_NODES) {
            union { uint4 u; __nv_bfloat162 h[4]; } pk;
#pragma unroll
            for (int p = 0; p < 4; p++)
                pk.h[p] = __floats2bfloat162_rn(acc[m][2 * p], acc[m][2 * p + 1]);
            *(uint4*)(g_hw1 + (size_t)row * D_H1 + c0) = pk.u;
        }
    }
}

// ---------------- gather L0: warp/node, uniform CSR loads, fused bias+relu ----
__global__ void k_gather0(const float* __restrict__ b0) {
    int warp = (blockIdx.x * blockDim.x + threadIdx.x) >> 5;
    int lane = threadIdx.x & 31;
    if (warp >= N_NODES) return;
    const int node = warp;
    float inv_r = g_inv[node];
    int start = (node == 0) ? 0 : g_off[node - 1];
    int end = g_off[node];

    const __nv_bfloat162* hw = (const __nv_bfloat162*)g_hw0;
    float2 self = __bfloat1622float2(hw[(size_t)node * 32 + lane]);
    float tx = inv_r * self.x, ty = inv_r * self.y;

#pragma unroll 8
    for (int idx = start; idx < end; idx++) {
        int2 p = g_csr[idx];               // warp-uniform -> L1 broadcast
        float w = __int_as_float(p.y);
        float2 v = __bfloat1622float2(hw[(size_t)p.x * 32 + lane]);
        tx += w * v.x; ty += w * v.y;
    }

    float2 b = ((const float2*)b0)[lane];
    float ox = fmaxf(inv_r * tx + b.x, 0.f);
    float oy = fmaxf(inv_r * ty + b.y, 0.f);
    ((__nv_bfloat162*)g_h0)[(size_t)node * 32 + lane] = __floats2bfloat162_rn(ox, oy);
}

// ---------------- gather L1: half-warp per edge (2 edges/iter) ----------------
// Row = 32 bf16 = 16 bf16x2 = 64B; lanes 0-15 handle edge idx, 16-31 edge idx+1.
__global__ void k_gather1(const int* __restrict__ ngi, const float* __restrict__ b1) {
    int warp = (blockIdx.x * blockDim.x + threadIdx.x) >> 5;
    int lane = threadIdx.x & 31;
    if (warp >= N_NODES) return;
    const int node = warp;
    const int sub  = lane & 15;
    const int half = lane >> 4;
    float inv_r = g_inv[node];
    int start = (node == 0) ? 0 : g_off[node - 1];
    int end = g_off[node];

    const __nv_bfloat162* hw = (const __nv_bfloat162*)g_hw1;  // 16 pairs per row

    float tx = 0.f, ty = 0.f;
    if (half == 0) {                        // self-loop term once
        float2 s = __bfloat1622float2(hw[(size_t)node * 16 + sub]);
        tx = inv_r * s.x; ty = inv_r * s.y;
    }

#pragma unroll 4
    for (int idx2 = start; idx2 < end; idx2 += 2) {
        int   myidx = idx2 + half;
        bool  valid = myidx < end;
        int2  p = valid ? g_csr[myidx] : make_int2(0, 0);
        float w = valid ? __int_as_float(p.y) : 0.f;
        float2 v = __bfloat1622float2(hw[(size_t)p.x * 16 + sub]);
        tx += w * v.x; ty += w * v.y;
    }

    // combine the two halves (lanes 0-15 end up with full sums)
    tx += __shfl_down_sync(0xffffffffu, tx, 16);
    ty += __shfl_down_sync(0xffffffffu, ty, 16);

    if (half == 0) {
        float2 b = ((const float2*)b1)[sub];
        float hx = fmaxf(inv_r * tx + b.x, 0.f);
        float hy = fmaxf(inv_r * ty + b.y, 0.f);
        int g = ngi[node];
        float* dst = g_pool + (size_t)g * D_H1 + 2 * sub;
        asm volatile("red.global.add.v2.f32 [%0], {%1,%2};"
                     :: "l"(dst), "f"(hx), "f"(hy) : "memory");
    }
}

// ---------------- per-graph mean + dense head + state re-zero ----------------
__global__ void k_head(const int* __restrict__ ngi,
                       const float* __restrict__ Wd,
                       const float* __restrict__ bd,
                       float* __restrict__ out) {
    const int g = blockIdx.x;
    const int lane = threadIdx.x;     // 32 threads

    int lo = 0, hi = N_NODES;
    while (lo < hi) { int mid = (lo + hi) >> 1; if (ngi[mid] < g) lo = mid + 1; else hi = mid; }
    int start = lo;
    hi = N_NODES;
    while (lo < hi) { int mid = (lo + hi) >> 1; if (ngi[mid] < g + 1) lo = mid + 1; else hi = mid; }
    int end = lo;

    float cnt = (float)((end - start) > 0 ? (end - start) : 1);
    __shared__ float ps[D_H1];
    float pv = g_pool[(size_t)g * D_H1 + lane];
    ps[lane] = pv / cnt;
    g_pool[(size_t)g * D_H1 + lane] = 0.f;      // re-zero own slice for next replay
    __syncwarp();

    if (lane < N_CLASSES) {
        float s = bd[lane];
#pragma unroll
        for (int c = 0; c < D_H1; c++)
            s += ps[c] * Wd[c * N_CLASSES + lane];
        out[(size_t)g * N_CLASSES + lane] = s;
    }

    // re-zero degree counters for next replay (nobody reads g_cnt here)
    for (int i = g * 32 + lane; i < N_NODES; i += N_GRAPHS * 32) g_cnt[i] = 0;
}

// ---------------- launch ----------------
extern "C" void kernel_launch(void* const* d_in, const int* in_sizes, int n_in,
                              void* d_out, int out_size) {
    const float* x   = (const float*)d_in[0];
    const int*   ei  = (const int*)d_in[1];   // [2, E], int32
    const int*   ngi = (const int*)d_in[2];   // [N], int32, sorted
    const float* W0  = (const float*)d_in[3];
    const float* b0  = (const float*)d_in[4];
    const float* W1  = (const float*)d_in[5];
    const float* b1  = (const float*)d_in[6];
    const float* Wd  = (const float*)d_in[7];
    const float* bd  = (const float*)d_in[8];
    float*       out = (float*)d_out;

    const int T = 256;

    // degree + CSR build (g_cnt is zero on entry: load-time init / tail re-zero)
    k_cnt<<<(N_EDGES / 2 + T - 1) / T, T>>>(ei);
    k_scan1<<<SCAN_NB, SCAN_BLK>>>();
    k_scan23<<<SCAN_NB, SCAN_BLK>>>();
    k_fill<<<(N_EDGES / 2 + T - 1) / T, T>>>(ei);

    // layer 0
    k_gemm0<<<(N_NODES + 127) / 128, 256>>>(x, W0);
    k_gather0<<<(N_NODES * 32 + T - 1) / T, T>>>(b0);

    // layer 1
    k_gemm1<<<(N_NODES + 127) / 128, 128>>>(W1);
    k_gather1<<<(N_NODES * 32 + T - 1) / T, T>>>(ngi, b1);

    // pooled head (+ re-zero g_pool / g_cnt for next replay)
    k_head<<<N_GRAPHS, 32>>>(ngi, Wd, bd, out);
}

// round 10
// speedup vs baseline: 2.3607x; 1.0226x over previous
#include <cuda_runtime.h>
#include <cuda_bf16.h>

#define N_NODES   100000
#define N_EDGES   3200000
#define D_IN      128
#define D_H0      64
#define D_H1      32
#define N_GRAPHS  1024
#define N_CLASSES 16

#define SCAN_BLK  512
#define SCAN_NB   ((N_NODES + SCAN_BLK - 1) / SCAN_BLK)   // 196

// ---------------- scratch (static __device__, allocation-free) ----------------
// g_cnt and g_pool must be ZERO on entry: zero-init at module load (first call),
// and k_head re-zeros them at the end of every call -> identical pre-state per replay.
__device__ int   g_cnt[N_NODES];                 // in-degree (no self loop)
__device__ float g_inv[N_NODES];                 // rsqrt(deg+1)
__device__ int   g_off[N_NODES];                 // excl scan; mutated by fill -> end offsets
__device__ int   g_bsum[SCAN_NB];
__device__ int   g_csr[N_EDGES];                 // source node per CSR slot (4B entries)
__device__ __nv_bfloat16 g_hw0[N_NODES * D_H0];  // x @ W0   (bf16 payload)
__device__ __nv_bfloat16 g_h0 [N_NODES * D_H0];  // relu(agg0 + b0)  (bf16, feeds gemm1 only)
__device__ __nv_bfloat16 g_hw1[N_NODES * D_H1];  // h0 @ W1  (bf16 payload)
__device__ float g_pool[N_GRAPHS * D_H1];        // per-graph sums (fp32 red.add)

// ---------------- degree (2 edges / thread) ----------------
__global__ void k_cnt(const int* __restrict__ ei) {
    int e2 = blockIdx.x * blockDim.x + threadIdx.x;
    if (e2 < N_EDGES / 2) {
        int2 r = ((const int2*)ei)[e2];
        atomicAdd(&g_cnt[r.x], 1);
        atomicAdd(&g_cnt[r.y], 1);
    }
}

// ---------------- scan phase 1: per-block scan + inv ----------------
__global__ void k_scan1() {
    __shared__ int s[SCAN_BLK];
    int t = threadIdx.x;
    int i = blockIdx.x * SCAN_BLK + t;
    int v = (i < N_NODES) ? g_cnt[i] : 0;
    if (i < N_NODES) g_inv[i] = rsqrtf((float)(v + 1));
    s[t] = v;
    __syncthreads();
    for (int off = 1; off < SCAN_BLK; off <<= 1) {
        int tmp = (t >= off) ? s[t - off] : 0;
        __syncthreads();
        s[t] += tmp;
        __syncthreads();
    }
    if (i < N_NODES) g_off[i] = s[t] - v;       // exclusive within block
    if (t == SCAN_BLK - 1) g_bsum[blockIdx.x] = s[t];
}

// ---------------- scan phase 2+3 fused: each block sums its own prefix -------
__global__ void k_scan23() {
    __shared__ int s_pre;
    const int bid = blockIdx.x;
    if (threadIdx.x < 32) {
        int lane = threadIdx.x;
        int sum = 0;
        for (int b = lane; b < bid; b += 32) sum += g_bsum[b];
#pragma unroll
        for (int off = 16; off; off >>= 1) sum += __shfl_xor_sync(0xffffffffu, sum, off);
        if (lane == 0) s_pre = sum;
    }
    __syncthreads();
    int i = bid * SCAN_BLK + threadIdx.x;
    if (i < N_NODES) g_off[i] += s_pre;
}

// ---------------- CSR fill (2 edges / thread): col only, 4B entries ----------
__global__ void k_fill(const int* __restrict__ ei) {
    int e2 = blockIdx.x * blockDim.x + threadIdx.x;
    if (e2 < N_EDGES / 2) {
        int2 r = ((const int2*)ei)[e2];
        int2 c = ((const int2*)(ei + N_EDGES))[e2];
        int s0 = atomicAdd(&g_off[r.x], 1);
        g_csr[s0] = c.x;
        int s1 = atomicAdd(&g_off[r.y], 1);
        g_csr[s1] = c.y;
    }
}

// ---------------- GEMM0: hw0 = x[N,128] @ W0[128,64] -> bf16 ----------------
__global__ __launch_bounds__(256) void k_gemm0(const float* __restrict__ x,
                                               const float* __restrict__ W0) {
    __shared__ float xs[128 * 36];   // 18 KB, padded stride 36
    __shared__ float ws[32 * 64];    //  8 KB
    const int t  = threadIdx.x;
    const int rg = t >> 3;
    const int c0 = (t & 7) * 8;
    const int rbase = blockIdx.x * 128;

    float acc[4][8];
#pragma unroll
    for (int m = 0; m < 4; m++)
#pragma unroll
        for (int j = 0; j < 8; j++) acc[m][j] = 0.f;

    for (int kc = 0; kc < 4; kc++) {
#pragma unroll
        for (int i = t; i < 1024; i += 256) {
            int row = i >> 3, kk = i & 7;
            int grow = rbase + row;
            float4 v = make_float4(0.f, 0.f, 0.f, 0.f);
            if (grow < N_NODES)
                v = *(const float4*)(x + (size_t)grow * D_IN + kc * 32 + kk * 4);
            *(float4*)(xs + row * 36 + kk * 4) = v;
        }
#pragma unroll
        for (int i = t; i < 512; i += 256)
            *(float4*)(ws + i * 4) = *(const float4*)(W0 + (size_t)kc * 32 * D_H0 + i * 4);
        __syncthreads();

#pragma unroll
        for (int k4 = 0; k4 < 8; k4++) {
            float4 xv[4];
#pragma unroll
            for (int m = 0; m < 4; m++)
                xv[m] = *(const float4*)(xs + (rg + 32 * m) * 36 + k4 * 4);
#pragma unroll
            for (int kk = 0; kk < 4; kk++) {
                float4 wa = *(const float4*)(ws + (k4 * 4 + kk) * 64 + c0);
                float4 wb = *(const float4*)(ws + (k4 * 4 + kk) * 64 + c0 + 4);
#pragma unroll
                for (int m = 0; m < 4; m++) {
                    float xb = (kk == 0) ? xv[m].x : (kk == 1) ? xv[m].y
                             : (kk == 2) ? xv[m].z : xv[m].w;
                    acc[m][0] += xb * wa.x; acc[m][1] += xb * wa.y;
                    acc[m][2] += xb * wa.z; acc[m][3] += xb * wa.w;
                    acc[m][4] += xb * wb.x; acc[m][5] += xb * wb.y;
                    acc[m][6] += xb * wb.z; acc[m][7] += xb * wb.w;
                }
            }
        }
        __syncthreads();
    }
#pragma unroll
    for (int m = 0; m < 4; m++) {
        int row = rbase + rg + 32 * m;
        if (row < N_NODES) {
            union { uint4 u; __nv_bfloat162 h[4]; } pk;
#pragma unroll
            for (int p = 0; p < 4; p++)
                pk.h[p] = __floats2bfloat162_rn(acc[m][2 * p], acc[m][2 * p + 1]);
            *(uint4*)(g_hw0 + (size_t)row * D_H0 + c0) = pk.u;
        }
    }
}

// ---------------- GEMM1: hw1 = h0[N,64](bf16) @ W1[64,32] -> bf16 ----------------
__global__ __launch_bounds__(128) void k_gemm1(const float* __restrict__ W1) {
    __shared__ float xs[128 * 36];   // 18 KB
    __shared__ float ws[32 * 32];    //  4 KB
    const int t  = threadIdx.x;
    const int rg = t >> 2;
    const int c0 = (t & 3) * 8;
    const int rbase = blockIdx.x * 128;

    float acc[4][8];
#pragma unroll
    for (int m = 0; m < 4; m++)
#pragma unroll
        for (int j = 0; j < 8; j++) acc[m][j] = 0.f;

    for (int kc = 0; kc < 2; kc++) {
#pragma unroll
        for (int i = t; i < 512; i += 128) {
            int row = i >> 2, kk = i & 3;
            int grow = rbase + row;
            uint4 raw = make_uint4(0, 0, 0, 0);
            if (grow < N_NODES)
                raw = *(const uint4*)(g_h0 + (size_t)grow * D_H0 + kc * 32 + kk * 8);
            const __nv_bfloat162* hp = (const __nv_bfloat162*)&raw;
            float2 f0 = __bfloat1622float2(hp[0]);
            float2 f1 = __bfloat1622float2(hp[1]);
            float2 f2 = __bfloat1622float2(hp[2]);
            float2 f3 = __bfloat1622float2(hp[3]);
            *(float4*)(xs + row * 36 + kk * 8)     = make_float4(f0.x, f0.y, f1.x, f1.y);
            *(float4*)(xs + row * 36 + kk * 8 + 4) = make_float4(f2.x, f2.y, f3.x, f3.y);
        }
#pragma unroll
        for (int i = t; i < 256; i += 128)
            *(float4*)(ws + i * 4) = *(const float4*)(W1 + (size_t)kc * 32 * D_H1 + i * 4);
        __syncthreads();

#pragma unroll
        for (int k4 = 0; k4 < 8; k4++) {
            float4 xv[4];
#pragma unroll
            for (int m = 0; m < 4; m++)
                xv[m] = *(const float4*)(xs + (rg + 32 * m) * 36 + k4 * 4);
#pragma unroll
            for (int kk = 0; kk < 4; kk++) {
                float4 wa = *(const float4*)(ws + (k4 * 4 + kk) * 32 + c0);
                float4 wb = *(const float4*)(ws + (k4 * 4 + kk) * 32 + c0 + 4);
#pragma unroll
                for (int m = 0; m < 4; m++) {
                    float xb = (kk == 0) ? xv[m].x : (kk == 1) ? xv[m].y
                             : (kk == 2) ? xv[m].z : xv[m].w;
                    acc[m][0] += xb * wa.x; acc[m][1] += xb * wa.y;
                    acc[m][2] += xb * wa.z; acc[m][3] += xb * wa.w;
                    acc[m][4] += xb * wb.x; acc[m][5] += xb * wb.y;
                    acc[m][6] += xb * wb.z; acc[m][7] += xb * wb.w;
                }
            }
        }
        __syncthreads();
    }
#pragma unroll
    for (int m = 0; m < 4; m++) {
        int row = rbase + rg + 32 * m;
        if (row < N_NODES) {
            union { uint4 u; __nv_bfloat162 h[4]; } pk;
#pragma unroll
            for (int p = 0; p < 4; p++)
                pk.h[p] = __floats2bfloat162_rn(acc[m][2 * p], acc[m][2 * p + 1]);
            *(uint4*)(g_hw1 + (size_t)row * D_H1 + c0) = pk.u;
        }
    }
}

// ---------------- gather L0: warp/node, uniform CSR+inv loads, fused bias+relu
__global__ void k_gather0(const float* __restrict__ b0) {
    int warp = (blockIdx.x * blockDim.x + threadIdx.x) >> 5;
    int lane = threadIdx.x & 31;
    if (warp >= N_NODES) return;
    const int node = warp;
    float inv_r = g_inv[node];
    int start = (node == 0) ? 0 : g_off[node - 1];
    int end = g_off[node];

    const __nv_bfloat162* hw = (const __nv_bfloat162*)g_hw0;
    float2 self = __bfloat1622float2(hw[(size_t)node * 32 + lane]);
    float tx = inv_r * self.x, ty = inv_r * self.y;

#pragma unroll 8
    for (int idx = start; idx < end; idx++) {
        int p = g_csr[idx];                // warp-uniform -> L1 broadcast
        float w = g_inv[p];                // warp-uniform
        float2 v = __bfloat1622float2(hw[(size_t)p * 32 + lane]);
        tx += w * v.x; ty += w * v.y;
    }

    float2 b = ((const float2*)b0)[lane];
    float ox = fmaxf(inv_r * tx + b.x, 0.f);
    float oy = fmaxf(inv_r * ty + b.y, 0.f);
    ((__nv_bfloat162*)g_h0)[(size_t)node * 32 + lane] = __floats2bfloat162_rn(ox, oy);
}

// ---------------- gather L1: half-warp per edge (2 edges/iter) ----------------
__global__ void k_gather1(const int* __restrict__ ngi, const float* __restrict__ b1) {
    int warp = (blockIdx.x * blockDim.x + threadIdx.x) >> 5;
    int lane = threadIdx.x & 31;
    if (warp >= N_NODES) return;
    const int node = warp;
    const int sub  = lane & 15;
    const int half = lane >> 4;
    float inv_r = g_inv[node];
    int start = (node == 0) ? 0 : g_off[node - 1];
    int end = g_off[node];

    const __nv_bfloat162* hw = (const __nv_bfloat162*)g_hw1;  // 16 pairs per row

    float tx = 0.f, ty = 0.f;
    if (half == 0) {                        // self-loop term once
        float2 s = __bfloat1622float2(hw[(size_t)node * 16 + sub]);
        tx = inv_r * s.x; ty = inv_r * s.y;
    }

#pragma unroll 4
    for (int idx2 = start; idx2 < end; idx2 += 2) {
        int   myidx = idx2 + half;
        bool  valid = myidx < end;
        int   p = valid ? g_csr[myidx] : 0;
        float w = valid ? g_inv[p] : 0.f;
        float2 v = __bfloat1622float2(hw[(size_t)p * 16 + sub]);
        tx += w * v.x; ty += w * v.y;
    }

    tx += __shfl_down_sync(0xffffffffu, tx, 16);
    ty += __shfl_down_sync(0xffffffffu, ty, 16);

    if (half == 0) {
        float2 b = ((const float2*)b1)[sub];
        float hx = fmaxf(inv_r * tx + b.x, 0.f);
        float hy = fmaxf(inv_r * ty + b.y, 0.f);
        int g = ngi[node];
        float* dst = g_pool + (size_t)g * D_H1 + 2 * sub;
        asm volatile("red.global.add.v2.f32 [%0], {%1,%2};"
                     :: "l"(dst), "f"(hx), "f"(hy) : "memory");
    }
}

// ---------------- per-graph mean + dense head + state re-zero ----------------
__global__ void k_head(const int* __restrict__ ngi,
                       const float* __restrict__ Wd,
                       const float* __restrict__ bd,
                       float* __restrict__ out) {
    const int g = blockIdx.x;
    const int lane = threadIdx.x;     // 32 threads

    int lo = 0, hi = N_NODES;
    while (lo < hi) { int mid = (lo + hi) >> 1; if (ngi[mid] < g) lo = mid + 1; else hi = mid; }
    int start = lo;
    hi = N_NODES;
    while (lo < hi) { int mid = (lo + hi) >> 1; if (ngi[mid] < g + 1) lo = mid + 1; else hi = mid; }
    int end = lo;

    float cnt = (float)((end - start) > 0 ? (end - start) : 1);
    __shared__ float ps[D_H1];
    float pv = g_pool[(size_t)g * D_H1 + lane];
    ps[lane] = pv / cnt;
    g_pool[(size_t)g * D_H1 + lane] = 0.f;      // re-zero own slice for next replay
    __syncwarp();

    if (lane < N_CLASSES) {
        float s = bd[lane];
#pragma unroll
        for (int c = 0; c < D_H1; c++)
            s += ps[c] * Wd[c * N_CLASSES + lane];
        out[(size_t)g * N_CLASSES + lane] = s;
    }

    // re-zero degree counters for next replay (nobody reads g_cnt here)
    for (int i = g * 32 + lane; i < N_NODES; i += N_GRAPHS * 32) g_cnt[i] = 0;
}

// ---------------- launch: fork gemm0 onto a side stream during CSR build -----
extern "C" void kernel_launch(void* const* d_in, const int* in_sizes, int n_in,
                              void* d_out, int out_size) {
    const float* x   = (const float*)d_in[0];
    const int*   ei  = (const int*)d_in[1];   // [2, E], int32
    const int*   ngi = (const int*)d_in[2];   // [N], int32, sorted
    const float* W0  = (const float*)d_in[3];
    const float* b0  = (const float*)d_in[4];
    const float* W1  = (const float*)d_in[5];
    const float* b1  = (const float*)d_in[6];
    const float* Wd  = (const float*)d_in[7];
    const float* bd  = (const float*)d_in[8];
    float*       out = (float*)d_out;

    const int T = 256;

    // Side stream + events for the gemm0 branch. Created fresh each call and
    // intentionally NOT destroyed: destroying a stream/event that is part of an
    // in-progress capture invalidates the capture, and kernel_launch is invoked
    // only a handful of times host-side (replays re-execute no host code).
    cudaStream_t s2;
    cudaStreamCreateWithFlags(&s2, cudaStreamNonBlocking);
    cudaEvent_t eFork, eJoin;
    cudaEventCreateWithFlags(&eFork, cudaEventDisableTiming);
    cudaEventCreateWithFlags(&eJoin, cudaEventDisableTiming);

    // fork: gemm0 (depends only on x, W0) runs concurrently with CSR build
    cudaEventRecord(eFork, 0);
    cudaStreamWaitEvent(s2, eFork, 0);
    k_gemm0<<<(N_NODES + 127) / 128, 256, 0, s2>>>(x, W0);
    cudaEventRecord(eJoin, s2);

    // CSR build on the main stream (g_cnt zero on entry; tail re-zeros)
    k_cnt<<<(N_EDGES / 2 + T - 1) / T, T>>>(ei);
    k_scan1<<<SCAN_NB, SCAN_BLK>>>();
    k_scan23<<<SCAN_NB, SCAN_BLK>>>();
    k_fill<<<(N_EDGES / 2 + T - 1) / T, T>>>(ei);

    // join: gather0 needs both hw0 (s2) and CSR (main)
    cudaStreamWaitEvent(0, eJoin, 0);
    k_gather0<<<(N_NODES * 32 + T - 1) / T, T>>>(b0);

    // layer 1
    k_gemm1<<<(N_NODES + 127) / 128, 128>>>(W1);
    k_gather1<<<(N_NODES * 32 + T - 1) / T, T>>>(ngi, b1);

    // pooled head (+ re-zero g_pool / g_cnt for next replay)
    k_head<<<N_GRAPHS, 32>>>(ngi, Wd, bd, out);
}

// round 11
// speedup vs baseline: 2.5865x; 1.0956x over previous
#include <cuda_runtime.h>
#include <cuda_bf16.h>

#define N_NODES   100000
#define N_EDGES   3200000
#define D_IN      128
#define D_H0      64
#define D_H1      32
#define N_GRAPHS  1024
#define N_CLASSES 16

#define SCAN_BLK  512
#define SCAN_NB   ((N_NODES + SCAN_BLK - 1) / SCAN_BLK)   // 196

// ---------------- scratch (static __device__, allocation-free) ----------------
// g_cnt and g_pool must be ZERO on entry: zero-init at module load (first call),
// and k_head re-zeros them at the end of every call -> identical pre-state per replay.
__device__ int   g_cnt[N_NODES];                 // in-degree (no self loop)
__device__ float g_inv[N_NODES];                 // rsqrt(deg+1)
__device__ int   g_off[N_NODES];                 // excl scan; mutated by fill -> end offsets
__device__ int   g_bsum[SCAN_NB];
__device__ int   g_csr[N_EDGES];                 // source node per CSR slot (4B entries)
__device__ __nv_bfloat16 g_hws0[N_NODES * D_H0]; // inv[i] * (x @ W0)[i]  (bf16, pre-scaled)
__device__ __nv_bfloat16 g_h0 [N_NODES * D_H0];  // relu(agg0 + b0)  (bf16, feeds gemm1 only)
__device__ __nv_bfloat16 g_hws1[N_NODES * D_H1]; // inv[i] * (h0 @ W1)[i] (bf16, pre-scaled)
__device__ float g_pool[N_GRAPHS * D_H1];        // per-graph sums (fp32 red.add)

// ---------------- degree (2 edges / thread) ----------------
__global__ void k_cnt(const int* __restrict__ ei) {
    int e2 = blockIdx.x * blockDim.x + threadIdx.x;
    if (e2 < N_EDGES / 2) {
        int2 r = ((const int2*)ei)[e2];
        atomicAdd(&g_cnt[r.x], 1);
        atomicAdd(&g_cnt[r.y], 1);
    }
}

// ---------------- scan phase 1: per-block scan + inv ----------------
__global__ void k_scan1() {
    __shared__ int s[SCAN_BLK];
    int t = threadIdx.x;
    int i = blockIdx.x * SCAN_BLK + t;
    int v = (i < N_NODES) ? g_cnt[i] : 0;
    if (i < N_NODES) g_inv[i] = rsqrtf((float)(v + 1));
    s[t] = v;
    __syncthreads();
    for (int off = 1; off < SCAN_BLK; off <<= 1) {
        int tmp = (t >= off) ? s[t - off] : 0;
        __syncthreads();
        s[t] += tmp;
        __syncthreads();
    }
    if (i < N_NODES) g_off[i] = s[t] - v;       // exclusive within block
    if (t == SCAN_BLK - 1) g_bsum[blockIdx.x] = s[t];
}

// ---------------- scan phase 2+3 fused: each block sums its own prefix -------
__global__ void k_scan23() {
    __shared__ int s_pre;
    const int bid = blockIdx.x;
    if (threadIdx.x < 32) {
        int lane = threadIdx.x;
        int sum = 0;
        for (int b = lane; b < bid; b += 32) sum += g_bsum[b];
#pragma unroll
        for (int off = 16; off; off >>= 1) sum += __shfl_xor_sync(0xffffffffu, sum, off);
        if (lane == 0) s_pre = sum;
    }
    __syncthreads();
    int i = bid * SCAN_BLK + threadIdx.x;
    if (i < N_NODES) g_off[i] += s_pre;
}

// ---------------- CSR fill (2 edges / thread): col only, 4B entries ----------
__global__ void k_fill(const int* __restrict__ ei) {
    int e2 = blockIdx.x * blockDim.x + threadIdx.x;
    if (e2 < N_EDGES / 2) {
        int2 r = ((const int2*)ei)[e2];
        int2 c = ((const int2*)(ei + N_EDGES))[e2];
        int s0 = atomicAdd(&g_off[r.x], 1);
        g_csr[s0] = c.x;
        int s1 = atomicAdd(&g_off[r.y], 1);
        g_csr[s1] = c.y;
    }
}

// ---------------- GEMM0: hws0 = inv[row] * (x[N,128] @ W0[128,64]) -> bf16 ----
__global__ __launch_bounds__(256) void k_gemm0(const float* __restrict__ x,
                                               const float* __restrict__ W0) {
    __shared__ float xs[128 * 36];   // 18 KB, padded stride 36
    __shared__ float ws[32 * 64];    //  8 KB
    const int t  = threadIdx.x;
    const int rg = t >> 3;
    const int c0 = (t & 7) * 8;
    const int rbase = blockIdx.x * 128;

    float acc[4][8];
#pragma unroll
    for (int m = 0; m < 4; m++)
#pragma unroll
        for (int j = 0; j < 8; j++) acc[m][j] = 0.f;

    for (int kc = 0; kc < 4; kc++) {
#pragma unroll
        for (int i = t; i < 1024; i += 256) {
            int row = i >> 3, kk = i & 7;
            int grow = rbase + row;
            float4 v = make_float4(0.f, 0.f, 0.f, 0.f);
            if (grow < N_NODES)
                v = *(const float4*)(x + (size_t)grow * D_IN + kc * 32 + kk * 4);
            *(float4*)(xs + row * 36 + kk * 4) = v;
        }
#pragma unroll
        for (int i = t; i < 512; i += 256)
            *(float4*)(ws + i * 4) = *(const float4*)(W0 + (size_t)kc * 32 * D_H0 + i * 4);
        __syncthreads();

#pragma unroll
        for (int k4 = 0; k4 < 8; k4++) {
            float4 xv[4];
#pragma unroll
            for (int m = 0; m < 4; m++)
                xv[m] = *(const float4*)(xs + (rg + 32 * m) * 36 + k4 * 4);
#pragma unroll
            for (int kk = 0; kk < 4; kk++) {
                float4 wa = *(const float4*)(ws + (k4 * 4 + kk) * 64 + c0);
                float4 wb = *(const float4*)(ws + (k4 * 4 + kk) * 64 + c0 + 4);
#pragma unroll
                for (int m = 0; m < 4; m++) {
                    float xb = (kk == 0) ? xv[m].x : (kk == 1) ? xv[m].y
                             : (kk == 2) ? xv[m].z : xv[m].w;
                    acc[m][0] += xb * wa.x; acc[m][1] += xb * wa.y;
                    acc[m][2] += xb * wa.z; acc[m][3] += xb * wa.w;
                    acc[m][4] += xb * wb.x; acc[m][5] += xb * wb.y;
                    acc[m][6] += xb * wb.z; acc[m][7] += xb * wb.w;
                }
            }
        }
        __syncthreads();
    }
#pragma unroll
    for (int m = 0; m < 4; m++) {
        int row = rbase + rg + 32 * m;
        if (row < N_NODES) {
            float sc = g_inv[row];           // pre-scale row by its inv (free epilogue)
            union { uint4 u; __nv_bfloat162 h[4]; } pk;
#pragma unroll
            for (int p = 0; p < 4; p++)
                pk.h[p] = __floats2bfloat162_rn(sc * acc[m][2 * p], sc * acc[m][2 * p + 1]);
            *(uint4*)(g_hws0 + (size_t)row * D_H0 + c0) = pk.u;
        }
    }
}

// ---------------- GEMM1: hws1 = inv[row] * (h0[N,64](bf16) @ W1[64,32]) -> bf16
__global__ __launch_bounds__(128) void k_gemm1(const float* __restrict__ W1) {
    __shared__ float xs[128 * 36];   // 18 KB
    __shared__ float ws[32 * 32];    //  4 KB
    const int t  = threadIdx.x;
    const int rg = t >> 2;
    const int c0 = (t & 3) * 8;
    const int rbase = blockIdx.x * 128;

    float acc[4][8];
#pragma unroll
    for (int m = 0; m < 4; m++)
#pragma unroll
        for (int j = 0; j < 8; j++) acc[m][j] = 0.f;

    for (int kc = 0; kc < 2; kc++) {
#pragma unroll
        for (int i = t; i < 512; i += 128) {
            int row = i >> 2, kk = i & 3;
            int grow = rbase + row;
            uint4 raw = make_uint4(0, 0, 0, 0);
            if (grow < N_NODES)
                raw = *(const uint4*)(g_h0 + (size_t)grow * D_H0 + kc * 32 + kk * 8);
            const __nv_bfloat162* hp = (const __nv_bfloat162*)&raw;
            float2 f0 = __bfloat1622float2(hp[0]);
            float2 f1 = __bfloat1622float2(hp[1]);
            float2 f2 = __bfloat1622float2(hp[2]);
            float2 f3 = __bfloat1622float2(hp[3]);
            *(float4*)(xs + row * 36 + kk * 8)     = make_float4(f0.x, f0.y, f1.x, f1.y);
            *(float4*)(xs + row * 36 + kk * 8 + 4) = make_float4(f2.x, f2.y, f3.x, f3.y);
        }
#pragma unroll
        for (int i = t; i < 256; i += 128)
            *(float4*)(ws + i * 4) = *(const float4*)(W1 + (size_t)kc * 32 * D_H1 + i * 4);
        __syncthreads();

#pragma unroll
        for (int k4 = 0; k4 < 8; k4++) {
            float4 xv[4];
#pragma unroll
            for (int m = 0; m < 4; m++)
                xv[m] = *(const float4*)(xs + (rg + 32 * m) * 36 + k4 * 4);
#pragma unroll
            for (int kk = 0; kk < 4; kk++) {
                float4 wa = *(const float4*)(ws + (k4 * 4 + kk) * 32 + c0);
                float4 wb = *(const float4*)(ws + (k4 * 4 + kk) * 32 + c0 + 4);
#pragma unroll
                for (int m = 0; m < 4; m++) {
                    float xb = (kk == 0) ? xv[m].x : (kk == 1) ? xv[m].y
                             : (kk == 2) ? xv[m].z : xv[m].w;
                    acc[m][0] += xb * wa.x; acc[m][1] += xb * wa.y;
                    acc[m][2] += xb * wa.z; acc[m][3] += xb * wa.w;
                    acc[m][4] += xb * wb.x; acc[m][5] += xb * wb.y;
                    acc[m][6] += xb * wb.z; acc[m][7] += xb * wb.w;
                }
            }
        }
        __syncthreads();
    }
#pragma unroll
    for (int m = 0; m < 4; m++) {
        int row = rbase + rg + 32 * m;
        if (row < N_NODES) {
            float sc = g_inv[row];           // pre-scale row by its inv
            union { uint4 u; __nv_bfloat162 h[4]; } pk;
#pragma unroll
            for (int p = 0; p < 4; p++)
                pk.h[p] = __floats2bfloat162_rn(sc * acc[m][2 * p], sc * acc[m][2 * p + 1]);
            *(uint4*)(g_hws1 + (size_t)row * D_H1 + c0) = pk.u;
        }
    }
}

// ---------------- gather L0: warp/node, pure adds; fused bias+relu -----------
// agg[r] = inv[r] * (hws0[r] + sum_{c in N(r)} hws0[c])
__global__ void k_gather0(const float* __restrict__ b0) {
    int warp = (blockIdx.x * blockDim.x + threadIdx.x) >> 5;
    int lane = threadIdx.x & 31;
    if (warp >= N_NODES) return;
    const int node = warp;
    float inv_r = g_inv[node];
    int start = (node == 0) ? 0 : g_off[node - 1];
    int end = g_off[node];

    const __nv_bfloat162* hw = (const __nv_bfloat162*)g_hws0;
    float2 self = __bfloat1622float2(hw[(size_t)node * 32 + lane]);
    float tx = self.x, ty = self.y;

#pragma unroll 8
    for (int idx = start; idx < end; idx++) {
        int p = g_csr[idx];                // warp-uniform -> L1 broadcast
        float2 v = __bfloat1622float2(hw[(size_t)p * 32 + lane]);
        tx += v.x; ty += v.y;
    }

    float2 b = ((const float2*)b0)[lane];
    float ox = fmaxf(inv_r * tx + b.x, 0.f);
    float oy = fmaxf(inv_r * ty + b.y, 0.f);
    ((__nv_bfloat162*)g_h0)[(size_t)node * 32 + lane] = __floats2bfloat162_rn(ox, oy);
}

// ---------------- gather L1: half-warp per edge (2 edges/iter), pure adds ----
__global__ void k_gather1(const int* __restrict__ ngi, const float* __restrict__ b1) {
    int warp = (blockIdx.x * blockDim.x + threadIdx.x) >> 5;
    int lane = threadIdx.x & 31;
    if (warp >= N_NODES) return;
    const int node = warp;
    const int sub  = lane & 15;
    const int half = lane >> 4;
    float inv_r = g_inv[node];
    int start = (node == 0) ? 0 : g_off[node - 1];
    int end = g_off[node];

    const __nv_bfloat162* hw = (const __nv_bfloat162*)g_hws1;  // 16 pairs per row

    float tx = 0.f, ty = 0.f;
    if (half == 0) {                        // self term once
        float2 s = __bfloat1622float2(hw[(size_t)node * 16 + sub]);
        tx = s.x; ty = s.y;
    }

#pragma unroll 4
    for (int idx2 = start; idx2 < end; idx2 += 2) {
        int   myidx = idx2 + half;
        bool  valid = myidx < end;
        int   p = valid ? g_csr[myidx] : 0;
        float msk = valid ? 1.f : 0.f;
        float2 v = __bfloat1622float2(hw[(size_t)p * 16 + sub]);
        tx += msk * v.x; ty += msk * v.y;
    }

    tx += __shfl_down_sync(0xffffffffu, tx, 16);
    ty += __shfl_down_sync(0xffffffffu, ty, 16);

    if (half == 0) {
        float2 b = ((const float2*)b1)[sub];
        float hx = fmaxf(inv_r * tx + b.x, 0.f);
        float hy = fmaxf(inv_r * ty + b.y, 0.f);
        int g = ngi[node];
        float* dst = g_pool + (size_t)g * D_H1 + 2 * sub;
        asm volatile("red.global.add.v2.f32 [%0], {%1,%2};"
                     :: "l"(dst), "f"(hx), "f"(hy) : "memory");
    }
}

// ---------------- per-graph mean + dense head + state re-zero ----------------
__global__ void k_head(const int* __restrict__ ngi,
                       const float* __restrict__ Wd,
                       const float* __restrict__ bd,
                       float* __restrict__ out) {
    const int g = blockIdx.x;
    const int lane = threadIdx.x;     // 32 threads

    int lo = 0, hi = N_NODES;
    while (lo < hi) { int mid = (lo + hi) >> 1; if (ngi[mid] < g) lo = mid + 1; else hi = mid; }
    int start = lo;
    hi = N_NODES;
    while (lo < hi) { int mid = (lo + hi) >> 1; if (ngi[mid] < g + 1) lo = mid + 1; else hi = mid; }
    int end = lo;

    float cnt = (float)((end - start) > 0 ? (end - start) : 1);
    __shared__ float ps[D_H1];
    float pv = g_pool[(size_t)g * D_H1 + lane];
    ps[lane] = pv / cnt;
    g_pool[(size_t)g * D_H1 + lane] = 0.f;      // re-zero own slice for next replay
    __syncwarp();

    if (lane < N_CLASSES) {
        float s = bd[lane];
#pragma unroll
        for (int c = 0; c < D_H1; c++)
            s += ps[c] * Wd[c * N_CLASSES + lane];
        out[(size_t)g * N_CLASSES + lane] = s;
    }

    // re-zero degree counters for next replay (nobody reads g_cnt here)
    for (int i = g * 32 + lane; i < N_NODES; i += N_GRAPHS * 32) g_cnt[i] = 0;
}

// ---------------- launch: fork gemm0 (needs inv) after scan1 ------------------
extern "C" void kernel_launch(void* const* d_in, const int* in_sizes, int n_in,
                              void* d_out, int out_size) {
    const float* x   = (const float*)d_in[0];
    const int*   ei  = (const int*)d_in[1];   // [2, E], int32
    const int*   ngi = (const int*)d_in[2];   // [N], int32, sorted
    const float* W0  = (const float*)d_in[3];
    const float* b0  = (const float*)d_in[4];
    const float* W1  = (const float*)d_in[5];
    const float* b1  = (const float*)d_in[6];
    const float* Wd  = (const float*)d_in[7];
    const float* bd  = (const float*)d_in[8];
    float*       out = (float*)d_out;

    const int T = 256;

    // Side stream + events; created per call, never destroyed (graph-capture safe;
    // host code runs only a handful of times, replays re-execute nothing host-side).
    cudaStream_t s2;
    cudaStreamCreateWithFlags(&s2, cudaStreamNonBlocking);
    cudaEvent_t eFork, eJoin;
    cudaEventCreateWithFlags(&eFork, cudaEventDisableTiming);
    cudaEventCreateWithFlags(&eJoin, cudaEventDisableTiming);

    // degree + inv (g_cnt zero on entry; tail re-zeros)
    k_cnt<<<(N_EDGES / 2 + T - 1) / T, T>>>(ei);
    k_scan1<<<SCAN_NB, SCAN_BLK>>>();

    // fork: gemm0 (reads x, W0, g_inv) overlaps scan23 + fill
    cudaEventRecord(eFork, 0);
    cudaStreamWaitEvent(s2, eFork, 0);
    k_gemm0<<<(N_NODES + 127) / 128, 256, 0, s2>>>(x, W0);
    cudaEventRecord(eJoin, s2);

    k_scan23<<<SCAN_NB, SCAN_BLK>>>();
    k_fill<<<(N_EDGES / 2 + T - 1) / T, T>>>(ei);

    // join: gather0 needs hws0 (s2) + CSR (main)
    cudaStreamWaitEvent(0, eJoin, 0);
    k_gather0<<<(N_NODES * 32 + T - 1) / T, T>>>(b0);

    // layer 1
    k_gemm1<<<(N_NODES + 127) / 128, 128>>>(W1);
    k_gather1<<<(N_NODES * 32 + T - 1) / T, T>>>(ngi, b1);

    // pooled head (+ re-zero g_pool / g_cnt for next replay)
    k_head<<<N_GRAPHS, 32>>>(ngi, Wd, bd, out);
}

// round 16
// speedup vs baseline: 2.7071x; 1.0466x over previous
#include <cuda_runtime.h>
#include <cuda_bf16.h>

#define N_NODES   100000
#define N_EDGES   3200000
#define D_IN      128
#define D_H0      64
#define D_H1      32
#define N_GRAPHS  1024
#define N_CLASSES 16

#define SCAN_BLK  512
#define SCAN_NB   ((N_NODES + SCAN_BLK - 1) / SCAN_BLK)   // 196

// ---------------- scratch (static __device__, allocation-free) ----------------
// g_cnt and g_pool must be ZERO on entry: zero-init at module load (first call),
// and k_head re-zeros them at the end of every call -> identical pre-state per replay.
__device__ int   g_cnt[N_NODES];                 // in-degree (no self loop)
__device__ float g_inv[N_NODES];                 // rsqrt(deg+1)
__device__ int   g_off[N_NODES];                 // excl scan; mutated by fill -> end offsets
__device__ int   g_bsum[SCAN_NB];
__device__ int   g_csr[N_EDGES];                 // source node per CSR slot (4B entries)
__device__ __nv_bfloat16 g_hws0[N_NODES * D_H0]; // inv[i] * (x @ W0)[i]  (bf16, pre-scaled)
__device__ __nv_bfloat16 g_h0 [N_NODES * D_H0];  // relu(agg0 + b0)  (bf16, feeds gemm1 only)
__device__ __nv_bfloat16 g_hws1[N_NODES * D_H1]; // inv[i] * (h0 @ W1)[i] (bf16, pre-scaled)
__device__ float g_pool[N_GRAPHS * D_H1];        // per-graph sums (fp32 red.add)

// ---------------- degree (2 edges / thread) ----------------
__global__ void k_cnt(const int* __restrict__ ei) {
    int e2 = blockIdx.x * blockDim.x + threadIdx.x;
    if (e2 < N_EDGES / 2) {
        int2 r = ((const int2*)ei)[e2];
        atomicAdd(&g_cnt[r.x], 1);
        atomicAdd(&g_cnt[r.y], 1);
    }
}

// ---------------- scan phase 1: per-block scan + inv ----------------
__global__ void k_scan1() {
    __shared__ int s[SCAN_BLK];
    int t = threadIdx.x;
    int i = blockIdx.x * SCAN_BLK + t;
    int v = (i < N_NODES) ? g_cnt[i] : 0;
    if (i < N_NODES) g_inv[i] = rsqrtf((float)(v + 1));
    s[t] = v;
    __syncthreads();
    for (int off = 1; off < SCAN_BLK; off <<= 1) {
        int tmp = (t >= off) ? s[t - off] : 0;
        __syncthreads();
        s[t] += tmp;
        __syncthreads();
    }
    if (i < N_NODES) g_off[i] = s[t] - v;       // exclusive within block
    if (t == SCAN_BLK - 1) g_bsum[blockIdx.x] = s[t];
}

// ---------------- scan phase 2+3 fused: each block sums its own prefix -------
__global__ void k_scan23() {
    __shared__ int s_pre;
    const int bid = blockIdx.x;
    if (threadIdx.x < 32) {
        int lane = threadIdx.x;
        int sum = 0;
        for (int b = lane; b < bid; b += 32) sum += g_bsum[b];
#pragma unroll
        for (int off = 16; off; off >>= 1) sum += __shfl_xor_sync(0xffffffffu, sum, off);
        if (lane == 0) s_pre = sum;
    }
    __syncthreads();
    int i = bid * SCAN_BLK + threadIdx.x;
    if (i < N_NODES) g_off[i] += s_pre;
}

// ---------------- CSR fill (2 edges / thread): col only, 4B entries ----------
__global__ void k_fill(const int* __restrict__ ei) {
    int e2 = blockIdx.x * blockDim.x + threadIdx.x;
    if (e2 < N_EDGES / 2) {
        int2 r = ((const int2*)ei)[e2];
        int2 c = ((const int2*)(ei + N_EDGES))[e2];
        int s0 = atomicAdd(&g_off[r.x], 1);
        g_csr[s0] = c.x;
        int s1 = atomicAdd(&g_off[r.y], 1);
        g_csr[s1] = c.y;
    }
}

// ---------------- GEMM0: hws0 = inv[row] * (x[N,128] @ W0[128,64]) -> bf16 ----
__global__ __launch_bounds__(256) void k_gemm0(const float* __restrict__ x,
                                               const float* __restrict__ W0) {
    __shared__ float xs[128 * 36];   // 18 KB, padded stride 36
    __shared__ float ws[32 * 64];    //  8 KB
    const int t  = threadIdx.x;
    const int rg = t >> 3;
    const int c0 = (t & 7) * 8;
    const int rbase = blockIdx.x * 128;

    float acc[4][8];
#pragma unroll
    for (int m = 0; m < 4; m++)
#pragma unroll
        for (int j = 0; j < 8; j++) acc[m][j] = 0.f;

    for (int kc = 0; kc < 4; kc++) {
#pragma unroll
        for (int i = t; i < 1024; i += 256) {
            int row = i >> 3, kk = i & 7;
            int grow = rbase + row;
            float4 v = make_float4(0.f, 0.f, 0.f, 0.f);
            if (grow < N_NODES)
                v = *(const float4*)(x + (size_t)grow * D_IN + kc * 32 + kk * 4);
            *(float4*)(xs + row * 36 + kk * 4) = v;
        }
#pragma unroll
        for (int i = t; i < 512; i += 256)
            *(float4*)(ws + i * 4) = *(const float4*)(W0 + (size_t)kc * 32 * D_H0 + i * 4);
        __syncthreads();

#pragma unroll
        for (int k4 = 0; k4 < 8; k4++) {
            float4 xv[4];
#pragma unroll
            for (int m = 0; m < 4; m++)
                xv[m] = *(const float4*)(xs + (rg + 32 * m) * 36 + k4 * 4);
#pragma unroll
            for (int kk = 0; kk < 4; kk++) {
                float4 wa = *(const float4*)(ws + (k4 * 4 + kk) * 64 + c0);
                float4 wb = *(const float4*)(ws + (k4 * 4 + kk) * 64 + c0 + 4);
#pragma unroll
                for (int m = 0; m < 4; m++) {
                    float xb = (kk == 0) ? xv[m].x : (kk == 1) ? xv[m].y
                             : (kk == 2) ? xv[m].z : xv[m].w;
                    acc[m][0] += xb * wa.x; acc[m][1] += xb * wa.y;
                    acc[m][2] += xb * wa.z; acc[m][3] += xb * wa.w;
                    acc[m][4] += xb * wb.x; acc[m][5] += xb * wb.y;
                    acc[m][6] += xb * wb.z; acc[m][7] += xb * wb.w;
                }
            }
        }
        __syncthreads();
    }
#pragma unroll
    for (int m = 0; m < 4; m++) {
        int row = rbase + rg + 32 * m;
        if (row < N_NODES) {
            float sc = g_inv[row];           // pre-scale row by its inv (free epilogue)
            union { uint4 u; __nv_bfloat162 h[4]; } pk;
#pragma unroll
            for (int p = 0; p < 4; p++)
                pk.h[p] = __floats2bfloat162_rn(sc * acc[m][2 * p], sc * acc[m][2 * p + 1]);
            *(uint4*)(g_hws0 + (size_t)row * D_H0 + c0) = pk.u;
        }
    }
}

// ---------------- GEMM1: hws1 = inv[row] * (h0[N,64](bf16) @ W1[64,32]) -> bf16
__global__ __launch_bounds__(128) void k_gemm1(const float* __restrict__ W1) {
    __shared__ float xs[128 * 36];   // 18 KB
    __shared__ float ws[32 * 32];    //  4 KB
    const int t  = threadIdx.x;
    const int rg = t >> 2;
    const int c0 = (t & 3) * 8;
    const int rbase = blockIdx.x * 128;

    float acc[4][8];
#pragma unroll
    for (int m = 0; m < 4; m++)
#pragma unroll
        for (int j = 0; j < 8; j++) acc[m][j] = 0.f;

    for (int kc = 0; kc < 2; kc++) {
#pragma unroll
        for (int i = t; i < 512; i += 128) {
            int row = i >> 2, kk = i & 3;
            int grow = rbase + row;
            uint4 raw = make_uint4(0, 0, 0, 0);
            if (grow < N_NODES)
                raw = *(const uint4*)(g_h0 + (size_t)grow * D_H0 + kc * 32 + kk * 8);
            const __nv_bfloat162* hp = (const __nv_bfloat162*)&raw;
            float2 f0 = __bfloat1622float2(hp[0]);
            float2 f1 = __bfloat1622float2(hp[1]);
            float2 f2 = __bfloat1622float2(hp[2]);
            float2 f3 = __bfloat1622float2(hp[3]);
            *(float4*)(xs + row * 36 + kk * 8)     = make_float4(f0.x, f0.y, f1.x, f1.y);
            *(float4*)(xs + row * 36 + kk * 8 + 4) = make_float4(f2.x, f2.y, f3.x, f3.y);
        }
#pragma unroll
        for (int i = t; i < 256; i += 128)
            *(float4*)(ws + i * 4) = *(const float4*)(W1 + (size_t)kc * 32 * D_H1 + i * 4);
        __syncthreads();

#pragma unroll
        for (int k4 = 0; k4 < 8; k4++) {
            float4 xv[4];
#pragma unroll
            for (int m = 0; m < 4; m++)
                xv[m] = *(const float4*)(xs + (rg + 32 * m) * 36 + k4 * 4);
#pragma unroll
            for (int kk = 0; kk < 4; kk++) {
                float4 wa = *(const float4*)(ws + (k4 * 4 + kk) * 32 + c0);
                float4 wb = *(const float4*)(ws + (k4 * 4 + kk) * 32 + c0 + 4);
#pragma unroll
                for (int m = 0; m < 4; m++) {
                    float xb = (kk == 0) ? xv[m].x : (kk == 1) ? xv[m].y
                             : (kk == 2) ? xv[m].z : xv[m].w;
                    acc[m][0] += xb * wa.x; acc[m][1] += xb * wa.y;
                    acc[m][2] += xb * wa.z; acc[m][3] += xb * wa.w;
                    acc[m][4] += xb * wb.x; acc[m][5] += xb * wb.y;
                    acc[m][6] += xb * wb.z; acc[m][7] += xb * wb.w;
                }
            }
        }
        __syncthreads();
    }
#pragma unroll
    for (int m = 0; m < 4; m++) {
        int row = rbase + rg + 32 * m;
        if (row < N_NODES) {
            float sc = g_inv[row];           // pre-scale row by its inv
            union { uint4 u; __nv_bfloat162 h[4]; } pk;
#pragma unroll
            for (int p = 0; p < 4; p++)
                pk.h[p] = __floats2bfloat162_rn(sc * acc[m][2 * p], sc * acc[m][2 * p + 1]);
            *(uint4*)(g_hws1 + (size_t)row * D_H1 + c0) = pk.u;
        }
    }
}

// ---------------- gather L0: half-warp per edge (2 edges/iter), pure adds -----
// Row = 64 bf16 = 16 uint2 (128B). Lanes 0-15 edge idx, lanes 16-31 edge idx+1.
// Each lane covers 4 columns (one uint2).
__global__ void k_gather0(const float* __restrict__ b0) {
    int warp = (blockIdx.x * blockDim.x + threadIdx.x) >> 5;
    int lane = threadIdx.x & 31;
    if (warp >= N_NODES) return;
    const int node = warp;
    const int sub  = lane & 15;
    const int half = lane >> 4;
    float inv_r = g_inv[node];
    int start = (node == 0) ? 0 : g_off[node - 1];
    int end = g_off[node];

    const uint2* hw = (const uint2*)g_hws0;   // 16 uint2 per row

    float t0 = 0.f, t1 = 0.f, t2 = 0.f, t3 = 0.f;
    if (half == 0) {                          // self term once
        uint2 s = hw[(size_t)node * 16 + sub];
        float2 a = __bfloat1622float2(*(const __nv_bfloat162*)&s.x);
        float2 b = __bfloat1622float2(*(const __nv_bfloat162*)&s.y);
        t0 = a.x; t1 = a.y; t2 = b.x; t3 = b.y;
    }

#pragma unroll 8
    for (int idx2 = start; idx2 < end; idx2 += 2) {
        int   myidx = idx2 + half;
        bool  valid = myidx < end;
        int   p   = valid ? g_csr[myidx] : 0;
        float msk = valid ? 1.f : 0.f;
        uint2 r = hw[(size_t)p * 16 + sub];
        float2 a = __bfloat1622float2(*(const __nv_bfloat162*)&r.x);
        float2 b = __bfloat1622float2(*(const __nv_bfloat162*)&r.y);
        t0 += msk * a.x; t1 += msk * a.y; t2 += msk * b.x; t3 += msk * b.y;
    }

    t0 += __shfl_down_sync(0xffffffffu, t0, 16);
    t1 += __shfl_down_sync(0xffffffffu, t1, 16);
    t2 += __shfl_down_sync(0xffffffffu, t2, 16);
    t3 += __shfl_down_sync(0xffffffffu, t3, 16);

    if (half == 0) {
        float4 b = ((const float4*)b0)[sub];
        float o0 = fmaxf(inv_r * t0 + b.x, 0.f);
        float o1 = fmaxf(inv_r * t1 + b.y, 0.f);
        float o2 = fmaxf(inv_r * t2 + b.z, 0.f);
        float o3 = fmaxf(inv_r * t3 + b.w, 0.f);
        __nv_bfloat162 h0 = __floats2bfloat162_rn(o0, o1);
        __nv_bfloat162 h1 = __floats2bfloat162_rn(o2, o3);
        uint2 o;
        o.x = *(const unsigned*)&h0;
        o.y = *(const unsigned*)&h1;
        ((uint2*)g_h0)[(size_t)node * 16 + sub] = o;
    }
}

// ---------------- gather L1: quarter-warp per edge (4 edges/iter) -------------
// Row = 32 bf16 = 8 uint2 (64B). Quarter q handles edge idx+q; lane covers 4 cols.
__global__ void k_gather1(const int* __restrict__ ngi, const float* __restrict__ b1) {
    int warp = (blockIdx.x * blockDim.x + threadIdx.x) >> 5;
    int lane = threadIdx.x & 31;
    if (warp >= N_NODES) return;
    const int node = warp;
    const int sub  = lane & 7;
    const int q    = lane >> 3;
    float inv_r = g_inv[node];
    int start = (node == 0) ? 0 : g_off[node - 1];
    int end = g_off[node];

    const uint2* hw = (const uint2*)g_hws1;   // 8 uint2 per row

    float t0 = 0.f, t1 = 0.f, t2 = 0.f, t3 = 0.f;
    if (q == 0) {                             // self term once
        uint2 s = hw[(size_t)node * 8 + sub];
        float2 a = __bfloat1622float2(*(const __nv_bfloat162*)&s.x);
        float2 b = __bfloat1622float2(*(const __nv_bfloat162*)&s.y);
        t0 = a.x; t1 = a.y; t2 = b.x; t3 = b.y;
    }

#pragma unroll 4
    for (int idx4 = start; idx4 < end; idx4 += 4) {
        int   myidx = idx4 + q;
        bool  valid = myidx < end;
        int   p   = valid ? g_csr[myidx] : 0;
        float msk = valid ? 1.f : 0.f;
        uint2 r = hw[(size_t)p * 8 + sub];
        float2 a = __bfloat1622float2(*(const __nv_bfloat162*)&r.x);
        float2 b = __bfloat1622float2(*(const __nv_bfloat162*)&r.y);
        t0 += msk * a.x; t1 += msk * a.y; t2 += msk * b.x; t3 += msk * b.y;
    }

    // combine quarters: q0 += q1+q2+q3
    t0 += __shfl_down_sync(0xffffffffu, t0, 8);
    t1 += __shfl_down_sync(0xffffffffu, t1, 8);
    t2 += __shfl_down_sync(0xffffffffu, t2, 8);
    t3 += __shfl_down_sync(0xffffffffu, t3, 8);
    t0 += __shfl_down_sync(0xffffffffu, t0, 16);
    t1 += __shfl_down_sync(0xffffffffu, t1, 16);
    t2 += __shfl_down_sync(0xffffffffu, t2, 16);
    t3 += __shfl_down_sync(0xffffffffu, t3, 16);

    if (q == 0) {
        float4 b = ((const float4*)b1)[sub];
        float h0 = fmaxf(inv_r * t0 + b.x, 0.f);
        float h1 = fmaxf(inv_r * t1 + b.y, 0.f);
        float h2 = fmaxf(inv_r * t2 + b.z, 0.f);
        float h3 = fmaxf(inv_r * t3 + b.w, 0.f);
        int g = ngi[node];
        float* dst = g_pool + (size_t)g * D_H1 + 4 * sub;
        asm volatile("red.global.add.v4.f32 [%0], {%1,%2,%3,%4};"
                     :: "l"(dst), "f"(h0), "f"(h1), "f"(h2), "f"(h3) : "memory");
    }
}

// ---------------- per-graph mean + dense head + state re-zero ----------------
__global__ void k_head(const int* __restrict__ ngi,
                       const float* __restrict__ Wd,
                       const float* __restrict__ bd,
                       float* __restrict__ out) {
    const int g = blockIdx.x;
    const int lane = threadIdx.x;     // 32 threads

    int lo = 0, hi = N_NODES;
    while (lo < hi) { int mid = (lo + hi) >> 1; if (ngi[mid] < g) lo = mid + 1; else hi = mid; }
    int start = lo;
    hi = N_NODES;
    while (lo < hi) { int mid = (lo + hi) >> 1; if (ngi[mid] < g + 1) lo = mid + 1; else hi = mid; }
    int end = lo;

    float cnt = (float)((end - start) > 0 ? (end - start) : 1);
    __shared__ float ps[D_H1];
    float pv = g_pool[(size_t)g * D_H1 + lane];
    ps[lane] = pv / cnt;
    g_pool[(size_t)g * D_H1 + lane] = 0.f;      // re-zero own slice for next replay
    __syncwarp();

    if (lane < N_CLASSES) {
        float s = bd[lane];
#pragma unroll
        for (int c = 0; c < D_H1; c++)
            s += ps[c] * Wd[c * N_CLASSES + lane];
        out[(size_t)g * N_CLASSES + lane] = s;
    }

    // re-zero degree counters for next replay (nobody reads g_cnt here)
    for (int i = g * 32 + lane; i < N_NODES; i += N_GRAPHS * 32) g_cnt[i] = 0;
}

// ---------------- launch: fork gemm0 (needs inv) after scan1 ------------------
extern "C" void kernel_launch(void* const* d_in, const int* in_sizes, int n_in,
                              void* d_out, int out_size) {
    const float* x   = (const float*)d_in[0];
    const int*   ei  = (const int*)d_in[1];   // [2, E], int32
    const int*   ngi = (const int*)d_in[2];   // [N], int32, sorted
    const float* W0  = (const float*)d_in[3];
    const float* b0  = (const float*)d_in[4];
    const float* W1  = (const float*)d_in[5];
    const float* b1  = (const float*)d_in[6];
    const float* Wd  = (const float*)d_in[7];
    const float* bd  = (const float*)d_in[8];
    float*       out = (float*)d_out;

    const int T = 256;

    // Side stream + events; created per call, never destroyed (graph-capture safe;
    // host code runs only a handful of times, replays re-execute nothing host-side).
    cudaStream_t s2;
    cudaStreamCreateWithFlags(&s2, cudaStreamNonBlocking);
    cudaEvent_t eFork, eJoin;
    cudaEventCreateWithFlags(&eFork, cudaEventDisableTiming);
    cudaEventCreateWithFlags(&eJoin, cudaEventDisableTiming);

    // degree + inv (g_cnt zero on entry; tail re-zeros)
    k_cnt<<<(N_EDGES / 2 + T - 1) / T, T>>>(ei);
    k_scan1<<<SCAN_NB, SCAN_BLK>>>();

    // fork: gemm0 (reads x, W0, g_inv) overlaps scan23 + fill
    cudaEventRecord(eFork, 0);
    cudaStreamWaitEvent(s2, eFork, 0);
    k_gemm0<<<(N_NODES + 127) / 128, 256, 0, s2>>>(x, W0);
    cudaEventRecord(eJoin, s2);

    k_scan23<<<SCAN_NB, SCAN_BLK>>>();
    k_fill<<<(N_EDGES / 2 + T - 1) / T, T>>>(ei);

    // join: gather0 needs hws0 (s2) + CSR (main)
    cudaStreamWaitEvent(0, eJoin, 0);
    k_gather0<<<(N_NODES * 32 + T - 1) / T, T>>>(b0);

    // layer 1
    k_gemm1<<<(N_NODES + 127) / 128, 128>>>(W1);
    k_gather1<<<(N_NODES * 32 + T - 1) / T, T>>>(ngi, b1);

    // pooled head (+ re-zero g_pool / g_cnt for next replay)
    k_head<<<N_GRAPHS, 32>>>(ngi, Wd, bd, out);
}